// round 1
// baseline (speedup 1.0000x reference)
#include <cuda_runtime.h>

#define B_ 16
#define S_ 512
#define D_ 1024
#define H_ 16
#define DK_ 64
#define MTOT (B_ * S_)   // 8192

// Scratch (alloc-free per harness rules): 4 x 32 MB
__device__ __align__(16) float g_q[(size_t)MTOT * D_];
__device__ __align__(16) float g_k[(size_t)MTOT * D_];
__device__ __align__(16) float g_v[(size_t)MTOT * D_];
__device__ __align__(16) float g_attn[(size_t)MTOT * D_];

// ---------------------------------------------------------------------------
// GEMM: C[M,N] = A[M,K] @ W[K,N] + bias[N]
// M=8192, N=K=1024 fixed. 128x128 block tile, BK=16, 8x8 microtile/thread.
// asel: 0 -> A = Aext (harness input), 1 -> A = g_attn
// csel: 0 -> C = Cext (d_out),        1/2/3 -> g_q/g_k/g_v
// ---------------------------------------------------------------------------
__global__ __launch_bounds__(256, 2)
void gemm_bias_kernel(const float* __restrict__ Aext,
                      const float* __restrict__ W,
                      const float* __restrict__ bias,
                      float* __restrict__ Cext,
                      int asel, int csel)
{
    const int M = MTOT, N = D_, K = D_;
    const float* A = (asel == 0) ? Aext : g_attn;
    float* C = (csel == 0) ? Cext : (csel == 1) ? g_q : (csel == 2) ? g_k : g_v;

    __shared__ __align__(16) float As[16][128];   // [k][m] (transposed A tile)
    __shared__ __align__(16) float Bs[16][128];   // [k][n]

    const int tid = threadIdx.x;
    const int tx = tid & 15;
    const int ty = tid >> 4;
    const int m0 = blockIdx.y * 128;
    const int n0 = blockIdx.x * 128;

    float acc[8][8];
#pragma unroll
    for (int i = 0; i < 8; i++)
#pragma unroll
        for (int j = 0; j < 8; j++) acc[i][j] = 0.f;

    for (int k0 = 0; k0 < K; k0 += 16) {
        // A tile: 128 rows x 16 cols -> As[k][m]
#pragma unroll
        for (int l = 0; l < 2; l++) {
            int idx = tid + l * 256;           // 0..511
            int row = idx >> 2;                // 0..127
            int cv  = (idx & 3) << 2;          // 0,4,8,12
            float4 a = *reinterpret_cast<const float4*>(
                &A[(size_t)(m0 + row) * K + k0 + cv]);
            As[cv + 0][row] = a.x;
            As[cv + 1][row] = a.y;
            As[cv + 2][row] = a.z;
            As[cv + 3][row] = a.w;
        }
        // B tile: 16 rows x 128 cols -> Bs[k][n] (vectorized, clean)
#pragma unroll
        for (int l = 0; l < 2; l++) {
            int idx = tid + l * 256;
            int row = idx >> 5;                // 0..15
            int cv  = (idx & 31) << 2;         // 0..124
            *reinterpret_cast<float4*>(&Bs[row][cv]) =
                *reinterpret_cast<const float4*>(
                    &W[(size_t)(k0 + row) * N + n0 + cv]);
        }
        __syncthreads();

#pragma unroll
        for (int kk = 0; kk < 16; kk++) {
            float a[8], b[8];
            *reinterpret_cast<float4*>(&a[0]) =
                *reinterpret_cast<const float4*>(&As[kk][ty * 4]);
            *reinterpret_cast<float4*>(&a[4]) =
                *reinterpret_cast<const float4*>(&As[kk][64 + ty * 4]);
            *reinterpret_cast<float4*>(&b[0]) =
                *reinterpret_cast<const float4*>(&Bs[kk][tx * 4]);
            *reinterpret_cast<float4*>(&b[4]) =
                *reinterpret_cast<const float4*>(&Bs[kk][64 + tx * 4]);
#pragma unroll
            for (int i = 0; i < 8; i++)
#pragma unroll
                for (int j = 0; j < 8; j++)
                    acc[i][j] += a[i] * b[j];
        }
        __syncthreads();
    }

    // Epilogue: + bias, vectorized stores
#pragma unroll
    for (int ih = 0; ih < 2; ih++) {
#pragma unroll
        for (int i = 0; i < 4; i++) {
            int row = m0 + ih * 64 + ty * 4 + i;
#pragma unroll
            for (int jh = 0; jh < 2; jh++) {
                int col = n0 + jh * 64 + tx * 4;
                float4 o;
                o.x = acc[ih * 4 + i][jh * 4 + 0] + bias[col + 0];
                o.y = acc[ih * 4 + i][jh * 4 + 1] + bias[col + 1];
                o.z = acc[ih * 4 + i][jh * 4 + 2] + bias[col + 2];
                o.w = acc[ih * 4 + i][jh * 4 + 3] + bias[col + 3];
                *reinterpret_cast<float4*>(&C[(size_t)row * N + col]) = o;
            }
        }
    }
}

// ---------------------------------------------------------------------------
// Fused attention per (b, h, 64-query tile). Flash-style online softmax.
// Q,K in smem transposed [d][row] (K XOR-swizzled), V natural [row][d].
// Threads: 16x16; each owns a 4x4 score microtile and 4x4 output microtile.
// PV done via warp shuffles of probability registers (no P staging buffer).
// Total smem = 3 * 16 KB = 48 KB exactly.
// ---------------------------------------------------------------------------
__global__ __launch_bounds__(256, 2)
void attn_kernel(const float* __restrict__ rel_table)
{
    __shared__ __align__(16) float Qs[DK_][64];   // [d][qrow]
    __shared__ __align__(16) float Ks[DK_][64];   // [d][kcol], xor-swizzled groups
    __shared__ __align__(16) float Vs[64][DK_];   // [krow][d]

    const int tid = threadIdx.x;
    const int tx = tid & 15;
    const int ty = tid >> 4;
    const int lane = tid & 31;
    const int qt = blockIdx.x;      // 0..7
    const int h  = blockIdx.y;      // 0..15
    const int b  = blockIdx.z;      // 0..15
    const int qi0 = qt * 64;
    const float scale = 0.125f;     // 1/sqrt(64)

    // Load Q tile transposed (one-time; 16-way store conflicts negligible)
    {
        const float* qbase = g_q + ((size_t)(b * S_ + qi0)) * D_ + h * DK_;
#pragma unroll
        for (int bt = 0; bt < 4; bt++) {
            int r  = (tid >> 4) + bt * 16;   // 0..63
            int d0 = (tid & 15) * 4;
            float4 qv = *reinterpret_cast<const float4*>(&qbase[(size_t)r * D_ + d0]);
            Qs[d0 + 0][r] = qv.x;
            Qs[d0 + 1][r] = qv.y;
            Qs[d0 + 2][r] = qv.z;
            Qs[d0 + 3][r] = qv.w;
        }
    }

    float O[4][4] = {};
    float mrow[4] = {-1e30f, -1e30f, -1e30f, -1e30f};
    float lrow[4] = {0.f, 0.f, 0.f, 0.f};

    for (int kt = 0; kt < 8; kt++) {
        const int kj0 = kt * 64;
        __syncthreads();   // Q visible (iter 0) / K,V consumers done (iter>0)

        const float* kbase = g_k + ((size_t)(b * S_ + kj0)) * D_ + h * DK_;
        const float* vbase = g_v + ((size_t)(b * S_ + kj0)) * D_ + h * DK_;
#pragma unroll
        for (int bt = 0; bt < 4; bt++) {
            int j  = (tid >> 4) + bt * 16;   // key row 0..63
            int d0 = (tid & 15) * 4;
            float4 kv = *reinterpret_cast<const float4*>(&kbase[(size_t)j * D_ + d0]);
            float kvv[4] = {kv.x, kv.y, kv.z, kv.w};
#pragma unroll
            for (int w = 0; w < 4; w++) {
                int d  = d0 + w;
                int pg = (j >> 2) ^ (d & 15);          // xor swizzle group
                Ks[d][pg * 4 + (j & 3)] = kvv[w];
            }
            *reinterpret_cast<float4*>(&Vs[j][d0]) =
                *reinterpret_cast<const float4*>(&vbase[(size_t)j * D_ + d0]);
        }
        __syncthreads();

        // S = Q K^T  (4x4 per thread; rows 4ty.., cols 4tx..)
        float s[4][4] = {};
#pragma unroll 16
        for (int d = 0; d < DK_; d++) {
            float4 q4 = *reinterpret_cast<const float4*>(&Qs[d][ty * 4]);
            float4 k4 = *reinterpret_cast<const float4*>(&Ks[d][(tx ^ (d & 15)) * 4]);
            float qa[4] = {q4.x, q4.y, q4.z, q4.w};
            float kb[4] = {k4.x, k4.y, k4.z, k4.w};
#pragma unroll
            for (int i = 0; i < 4; i++)
#pragma unroll
                for (int j = 0; j < 4; j++)
                    s[i][j] += qa[i] * kb[j];
        }

        // scale + relative-position bias, per-row tile max
        float mt[4], ls[4];
#pragma unroll
        for (int i = 0; i < 4; i++) {
            mt[i] = -1e30f;
            int gi = qi0 + ty * 4 + i;
#pragma unroll
            for (int j = 0; j < 4; j++) {
                int gj = kj0 + tx * 4 + j;
                float v = s[i][j] * scale +
                          __ldg(&rel_table[(size_t)(gi - gj + S_ - 1) * H_ + h]);
                s[i][j] = v;
                mt[i] = fmaxf(mt[i], v);
            }
        }
#pragma unroll
        for (int off = 8; off >= 1; off >>= 1)
#pragma unroll
            for (int i = 0; i < 4; i++)
                mt[i] = fmaxf(mt[i], __shfl_xor_sync(0xffffffffu, mt[i], off));

        // online softmax update
#pragma unroll
        for (int i = 0; i < 4; i++) {
            float mnew = fmaxf(mrow[i], mt[i]);
            float corr = __expf(mrow[i] - mnew);
            mrow[i] = mnew;
            lrow[i] *= corr;
#pragma unroll
            for (int j = 0; j < 4; j++) O[i][j] *= corr;
            float lsum = 0.f;
#pragma unroll
            for (int j = 0; j < 4; j++) {
                float p = __expf(s[i][j] - mnew);
                s[i][j] = p;
                lsum += p;
            }
            ls[i] = lsum;
        }
#pragma unroll
        for (int off = 8; off >= 1; off >>= 1)
#pragma unroll
            for (int i = 0; i < 4; i++)
                ls[i] += __shfl_xor_sync(0xffffffffu, ls[i], off);
#pragma unroll
        for (int i = 0; i < 4; i++) lrow[i] += ls[i];

        // O += P @ V via warp shuffles (broadcast p across the 16-lane group)
#pragma unroll
        for (int src = 0; src < 16; src++) {
            int srcLane = (lane & 16) | src;
#pragma unroll
            for (int jp = 0; jp < 4; jp++) {
                int jj = src * 4 + jp;
                float4 v4 = *reinterpret_cast<const float4*>(&Vs[jj][tx * 4]);
                float p0 = __shfl_sync(0xffffffffu, s[0][jp], srcLane);
                float p1 = __shfl_sync(0xffffffffu, s[1][jp], srcLane);
                float p2 = __shfl_sync(0xffffffffu, s[2][jp], srcLane);
                float p3 = __shfl_sync(0xffffffffu, s[3][jp], srcLane);
                O[0][0] += p0 * v4.x; O[0][1] += p0 * v4.y;
                O[0][2] += p0 * v4.z; O[0][3] += p0 * v4.w;
                O[1][0] += p1 * v4.x; O[1][1] += p1 * v4.y;
                O[1][2] += p1 * v4.z; O[1][3] += p1 * v4.w;
                O[2][0] += p2 * v4.x; O[2][1] += p2 * v4.y;
                O[2][2] += p2 * v4.z; O[2][3] += p2 * v4.w;
                O[3][0] += p3 * v4.x; O[3][1] += p3 * v4.y;
                O[3][2] += p3 * v4.z; O[3][3] += p3 * v4.w;
            }
        }
    }

    // Write normalized output tile
    float* obase = g_attn + ((size_t)(b * S_ + qi0)) * D_ + h * DK_;
#pragma unroll
    for (int i = 0; i < 4; i++) {
        float inv = 1.0f / lrow[i];
        float4 o = make_float4(O[i][0] * inv, O[i][1] * inv,
                               O[i][2] * inv, O[i][3] * inv);
        *reinterpret_cast<float4*>(&obase[(size_t)(ty * 4 + i) * D_ + tx * 4]) = o;
    }
}

// ---------------------------------------------------------------------------
// Launch
// ---------------------------------------------------------------------------
extern "C" void kernel_launch(void* const* d_in, const int* in_sizes, int n_in,
                              void* d_out, int out_size)
{
    const float* x   = (const float*)d_in[0];
    // d_in[1] = c (unused by the forward pass)
    const float* Wq  = (const float*)d_in[2];
    const float* bq  = (const float*)d_in[3];
    const float* Wk  = (const float*)d_in[4];
    const float* bk  = (const float*)d_in[5];
    const float* Wv  = (const float*)d_in[6];
    const float* bv  = (const float*)d_in[7];
    const float* Wo  = (const float*)d_in[8];
    const float* bo  = (const float*)d_in[9];
    const float* rel = (const float*)d_in[10];
    float* out = (float*)d_out;

    dim3 ggrid(D_ / 128, MTOT / 128);   // (8, 64)
    gemm_bias_kernel<<<ggrid, 256>>>(x, Wq, bq, nullptr, 0, 1);  // -> g_q
    gemm_bias_kernel<<<ggrid, 256>>>(x, Wk, bk, nullptr, 0, 2);  // -> g_k
    gemm_bias_kernel<<<ggrid, 256>>>(x, Wv, bv, nullptr, 0, 3);  // -> g_v

    dim3 agrid(S_ / 64, H_, B_);        // (8, 16, 16)
    attn_kernel<<<agrid, 256>>>(rel);   // -> g_attn

    gemm_bias_kernel<<<ggrid, 256>>>(nullptr, Wo, bo, out, 1, 0); // -> d_out
}

// round 3
// speedup vs baseline: 1.7395x; 1.7395x over previous
#include <cuda_runtime.h>
#include <cuda_bf16.h>
#include <cstdint>

#define B_ 16
#define S_ 512
#define D_ 1024
#define H_ 16
#define DK_ 64
#define MTOT (B_ * S_)   // 8192

// fp32 scratch
__device__ __align__(16) float g_q[(size_t)MTOT * D_];
__device__ __align__(16) float g_k[(size_t)MTOT * D_];
__device__ __align__(16) float g_v[(size_t)MTOT * D_];
__device__ __align__(16) float g_attn[(size_t)MTOT * D_];
// bf16 hi/lo split scratch
__device__ __align__(16) __nv_bfloat16 g_xhi[(size_t)MTOT * D_];
__device__ __align__(16) __nv_bfloat16 g_xlo[(size_t)MTOT * D_];
__device__ __align__(16) __nv_bfloat16 g_ahi[(size_t)MTOT * D_];
__device__ __align__(16) __nv_bfloat16 g_alo[(size_t)MTOT * D_];
__device__ __align__(16) __nv_bfloat16 g_wThi[(size_t)4 * D_ * D_];
__device__ __align__(16) __nv_bfloat16 g_wTlo[(size_t)4 * D_ * D_];

// ---------------------------------------------------------------------------
// Base-PTX helpers (NO tcgen05 — unsupported at compute_103 virtual arch)
// ---------------------------------------------------------------------------
__device__ __forceinline__ uint32_t smem_to_u32(const void* p) {
    uint32_t a;
    asm("{ .reg .u64 t; cvta.to.shared.u64 t, %1; cvt.u32.u64 %0, t; }"
        : "=r"(a) : "l"(p));
    return a;
}
#define CP_ASYNC16(d, s) \
    asm volatile("cp.async.cg.shared.global [%0], [%1], 16;" :: "r"(d), "l"(s))
#define CP_COMMIT() asm volatile("cp.async.commit_group;" ::: "memory")
#define CP_WAIT1()  asm volatile("cp.async.wait_group 1;" ::: "memory")
#define CP_WAIT0()  asm volatile("cp.async.wait_group 0;" ::: "memory")

__device__ __forceinline__ void ldsm4(uint32_t* r, uint32_t a) {
    asm volatile("ldmatrix.sync.aligned.m8n8.x4.shared.b16 {%0,%1,%2,%3}, [%4];"
                 : "=r"(r[0]), "=r"(r[1]), "=r"(r[2]), "=r"(r[3]) : "r"(a));
}
__device__ __forceinline__ void mma_bf16(float* c, const uint32_t* a,
                                         const uint32_t* b) {
    asm volatile(
        "mma.sync.aligned.m16n8k16.row.col.f32.bf16.bf16.f32 "
        "{%0,%1,%2,%3}, {%4,%5,%6,%7}, {%8,%9}, {%0,%1,%2,%3};"
        : "+f"(c[0]), "+f"(c[1]), "+f"(c[2]), "+f"(c[3])
        : "r"(a[0]), "r"(a[1]), "r"(a[2]), "r"(a[3]), "r"(b[0]), "r"(b[1]));
}

// Swizzled offset inside one 128x32-bf16 tile (8 KB). Two 64B logical rows
// per 128B physical row; 16B-chunk index XORed with phys row (8-group).
__device__ __forceinline__ uint32_t sw_off(int r, int c) {
    int p = r >> 1;
    int idx = (((r & 1) << 2) | c) ^ (p & 7);
    return (uint32_t)(p * 128 + idx * 16);
}

// ---------------------------------------------------------------------------
// Split fp32 -> bf16 hi/lo (elementwise). insel: 0=ext x, 1=g_attn.
// ---------------------------------------------------------------------------
__global__ void split_kernel(const float* __restrict__ ext, int insel, int outsel)
{
    const float* in = (insel == 0) ? ext : g_attn;
    __nv_bfloat16* hi = (outsel == 0) ? g_xhi : g_ahi;
    __nv_bfloat16* lo = (outsel == 0) ? g_xlo : g_alo;
    const int n4 = MTOT * D_ / 4;
    for (int i = blockIdx.x * blockDim.x + threadIdx.x; i < n4;
         i += gridDim.x * blockDim.x) {
        float4 v = reinterpret_cast<const float4*>(in)[i];
        __nv_bfloat16 h0 = __float2bfloat16(v.x), h1 = __float2bfloat16(v.y);
        __nv_bfloat16 h2 = __float2bfloat16(v.z), h3 = __float2bfloat16(v.w);
        __nv_bfloat16 l0 = __float2bfloat16(v.x - __bfloat162float(h0));
        __nv_bfloat16 l1 = __float2bfloat16(v.y - __bfloat162float(h1));
        __nv_bfloat16 l2 = __float2bfloat16(v.z - __bfloat162float(h2));
        __nv_bfloat16 l3 = __float2bfloat16(v.w - __bfloat162float(h3));
        reinterpret_cast<__nv_bfloat162*>(hi)[i * 2 + 0] = __halves2bfloat162(h0, h1);
        reinterpret_cast<__nv_bfloat162*>(hi)[i * 2 + 1] = __halves2bfloat162(h2, h3);
        reinterpret_cast<__nv_bfloat162*>(lo)[i * 2 + 0] = __halves2bfloat162(l0, l1);
        reinterpret_cast<__nv_bfloat162*>(lo)[i * 2 + 1] = __halves2bfloat162(l2, l3);
    }
}

// ---------------------------------------------------------------------------
// Transpose + split W [K][N] -> wT hi/lo [N][K] (bf16), slot widx
// ---------------------------------------------------------------------------
__global__ void wsplitT_kernel(const float* __restrict__ W, int widx)
{
    __shared__ float t[32][33];
    const int bx = blockIdx.x * 32;   // n tile
    const int by = blockIdx.y * 32;   // k tile
    const int tx = threadIdx.x, ty = threadIdx.y;
    for (int r = ty; r < 32; r += 8)
        t[r][tx] = W[(size_t)(by + r) * D_ + bx + tx];
    __syncthreads();
    __nv_bfloat16* hi = g_wThi + ((size_t)widx << 20);
    __nv_bfloat16* lo = g_wTlo + ((size_t)widx << 20);
    for (int r = ty; r < 32; r += 8) {
        float v = t[tx][r];                       // = W[by+tx][bx+r]
        __nv_bfloat16 h = __float2bfloat16(v);
        __nv_bfloat16 l = __float2bfloat16(v - __bfloat162float(h));
        size_t o = (size_t)(bx + r) * D_ + by + tx;
        hi[o] = h; lo[o] = l;
    }
}

// ---------------------------------------------------------------------------
// HMMA bf16x3 GEMM: C[8192,1024] = A @ W + bias (fp32-accurate).
// 128x128 block tile, BK=32, 16 warps (4x4), warp tile 32x32.
// 2-stage cp.async pipeline: stage = {Ah, Al, Bh, Bl} 8KB tiles = 32KB.
// ---------------------------------------------------------------------------
#define STAGE_BYTES 32768
#define GEMM_SMEM_BYTES (2 * STAGE_BYTES)

__global__ __launch_bounds__(512, 2)
void gemm_tc_kernel(const float* __restrict__ bias, float* __restrict__ Cext,
                    int asel, int widx, int csel)
{
    extern __shared__ char smc[];
    const int tid  = threadIdx.x;
    const int wid  = tid >> 5;
    const int lane = tid & 31;
    const int wm   = wid >> 2;          // 0..3
    const int wn   = wid & 3;           // 0..3
    const int n0   = blockIdx.x * 128;
    const int m0   = blockIdx.y * 128;
    const uint32_t smem_u = smem_to_u32(smc);

    const __nv_bfloat16* Ah = ((asel == 0) ? g_xhi : g_ahi) + (size_t)m0 * D_;
    const __nv_bfloat16* Al = ((asel == 0) ? g_xlo : g_alo) + (size_t)m0 * D_;
    const __nv_bfloat16* Bh = g_wThi + ((size_t)widx << 20) + (size_t)n0 * D_;
    const __nv_bfloat16* Bl = g_wTlo + ((size_t)widx << 20) + (size_t)n0 * D_;
    float* C = (csel == 0) ? Cext : (csel == 1) ? g_q : (csel == 2) ? g_k : g_v;

    // cp.async mapping: thread t -> row t>>2 (0..127), 16B chunk t&3
    const int lr = tid >> 2;
    const int lc = tid & 3;
    const uint32_t sdst = sw_off(lr, lc);
    const size_t gsrc = (size_t)lr * D_ + lc * 8;

    float acc[2][4][4];
#pragma unroll
    for (int i = 0; i < 2; i++)
#pragma unroll
        for (int j = 0; j < 4; j++)
#pragma unroll
            for (int k = 0; k < 4; k++) acc[i][j][k] = 0.f;

    // prologue: stage 0
    {
        const uint32_t sb = smem_u;
        CP_ASYNC16(sb +     0 + sdst, Ah + gsrc);
        CP_ASYNC16(sb +  8192 + sdst, Al + gsrc);
        CP_ASYNC16(sb + 16384 + sdst, Bh + gsrc);
        CP_ASYNC16(sb + 24576 + sdst, Bl + gsrc);
        CP_COMMIT();
    }

#pragma unroll 1
    for (int kc = 0; kc < 32; kc++) {
        if (kc + 1 < 32) {
            const uint32_t sb = smem_u + ((kc + 1) & 1) * STAGE_BYTES;
            const size_t go = gsrc + (size_t)(kc + 1) * 32;
            CP_ASYNC16(sb +     0 + sdst, Ah + go);
            CP_ASYNC16(sb +  8192 + sdst, Al + go);
            CP_ASYNC16(sb + 16384 + sdst, Bh + go);
            CP_ASYNC16(sb + 24576 + sdst, Bl + go);
            CP_COMMIT();
            CP_WAIT1();
        } else {
            CP_WAIT0();
        }
        __syncthreads();

        const uint32_t sb = smem_u + (kc & 1) * STAGE_BYTES;
#pragma unroll
        for (int s = 0; s < 2; s++) {
            uint32_t ah[2][4], al[2][4], bh[2][4], bl[2][4];
            const int arow = wm * 32 + (lane & 15);
            const int achk = 2 * s + (lane >> 4);
            ldsm4(ah[0], sb +     0 + sw_off(arow,      achk));
            ldsm4(ah[1], sb +     0 + sw_off(arow + 16, achk));
            ldsm4(al[0], sb +  8192 + sw_off(arow,      achk));
            ldsm4(al[1], sb +  8192 + sw_off(arow + 16, achk));
            const int brow = wn * 32 + (lane & 7) + ((lane >> 4) << 3);
            const int bchk = 2 * s + ((lane >> 3) & 1);
            ldsm4(bh[0], sb + 16384 + sw_off(brow,      bchk));
            ldsm4(bh[1], sb + 16384 + sw_off(brow + 16, bchk));
            ldsm4(bl[0], sb + 24576 + sw_off(brow,      bchk));
            ldsm4(bl[1], sb + 24576 + sw_off(brow + 16, bchk));
#pragma unroll
            for (int mt = 0; mt < 2; mt++) {
#pragma unroll
                for (int nt = 0; nt < 4; nt++) {
                    const uint32_t* bhp = &bh[nt >> 1][(nt & 1) * 2];
                    const uint32_t* blp = &bl[nt >> 1][(nt & 1) * 2];
                    mma_bf16(acc[mt][nt], ah[mt], bhp);
                    mma_bf16(acc[mt][nt], ah[mt], blp);
                    mma_bf16(acc[mt][nt], al[mt], bhp);
                }
            }
        }
        __syncthreads();   // protect stage buffers before next issue
    }

    // Epilogue: + bias, float2 stores
#pragma unroll
    for (int mt = 0; mt < 2; mt++) {
        const int row = m0 + wm * 32 + mt * 16 + (lane >> 2);
#pragma unroll
        for (int nt = 0; nt < 4; nt++) {
            const int col = n0 + wn * 32 + nt * 8 + (lane & 3) * 2;
            const float bx = bias[col], by = bias[col + 1];
            float2 o0 = make_float2(acc[mt][nt][0] + bx, acc[mt][nt][1] + by);
            float2 o1 = make_float2(acc[mt][nt][2] + bx, acc[mt][nt][3] + by);
            *reinterpret_cast<float2*>(&C[(size_t)row * D_ + col]) = o0;
            *reinterpret_cast<float2*>(&C[(size_t)(row + 8) * D_ + col]) = o1;
        }
    }
}

// ---------------------------------------------------------------------------
// Fused attention (round-1 proven: fp32 SIMT flash-style, 587us)
// ---------------------------------------------------------------------------
__global__ __launch_bounds__(256, 2)
void attn_kernel(const float* __restrict__ rel_table)
{
    __shared__ __align__(16) float Qs[DK_][64];
    __shared__ __align__(16) float Ks[DK_][64];
    __shared__ __align__(16) float Vs[64][DK_];

    const int tid = threadIdx.x;
    const int tx = tid & 15;
    const int ty = tid >> 4;
    const int lane = tid & 31;
    const int qt = blockIdx.x;
    const int h  = blockIdx.y;
    const int b  = blockIdx.z;
    const int qi0 = qt * 64;
    const float scale = 0.125f;

    {
        const float* qbase = g_q + ((size_t)(b * S_ + qi0)) * D_ + h * DK_;
#pragma unroll
        for (int bt = 0; bt < 4; bt++) {
            int r  = (tid >> 4) + bt * 16;
            int d0 = (tid & 15) * 4;
            float4 qv = *reinterpret_cast<const float4*>(&qbase[(size_t)r * D_ + d0]);
            Qs[d0 + 0][r] = qv.x;
            Qs[d0 + 1][r] = qv.y;
            Qs[d0 + 2][r] = qv.z;
            Qs[d0 + 3][r] = qv.w;
        }
    }

    float O[4][4] = {};
    float mrow[4] = {-1e30f, -1e30f, -1e30f, -1e30f};
    float lrow[4] = {0.f, 0.f, 0.f, 0.f};

    for (int kt = 0; kt < 8; kt++) {
        const int kj0 = kt * 64;
        __syncthreads();

        const float* kbase = g_k + ((size_t)(b * S_ + kj0)) * D_ + h * DK_;
        const float* vbase = g_v + ((size_t)(b * S_ + kj0)) * D_ + h * DK_;
#pragma unroll
        for (int bt = 0; bt < 4; bt++) {
            int j  = (tid >> 4) + bt * 16;
            int d0 = (tid & 15) * 4;
            float4 kv = *reinterpret_cast<const float4*>(&kbase[(size_t)j * D_ + d0]);
            float kvv[4] = {kv.x, kv.y, kv.z, kv.w};
#pragma unroll
            for (int w = 0; w < 4; w++) {
                int d  = d0 + w;
                int pg = (j >> 2) ^ (d & 15);
                Ks[d][pg * 4 + (j & 3)] = kvv[w];
            }
            *reinterpret_cast<float4*>(&Vs[j][d0]) =
                *reinterpret_cast<const float4*>(&vbase[(size_t)j * D_ + d0]);
        }
        __syncthreads();

        float s[4][4] = {};
#pragma unroll 16
        for (int d = 0; d < DK_; d++) {
            float4 q4 = *reinterpret_cast<const float4*>(&Qs[d][ty * 4]);
            float4 k4 = *reinterpret_cast<const float4*>(&Ks[d][(tx ^ (d & 15)) * 4]);
            float qa[4] = {q4.x, q4.y, q4.z, q4.w};
            float kb[4] = {k4.x, k4.y, k4.z, k4.w};
#pragma unroll
            for (int i = 0; i < 4; i++)
#pragma unroll
                for (int j = 0; j < 4; j++)
                    s[i][j] += qa[i] * kb[j];
        }

        float mt[4], ls[4];
#pragma unroll
        for (int i = 0; i < 4; i++) {
            mt[i] = -1e30f;
            int gi = qi0 + ty * 4 + i;
#pragma unroll
            for (int j = 0; j < 4; j++) {
                int gj = kj0 + tx * 4 + j;
                float v = s[i][j] * scale +
                          __ldg(&rel_table[(size_t)(gi - gj + S_ - 1) * H_ + h]);
                s[i][j] = v;
                mt[i] = fmaxf(mt[i], v);
            }
        }
#pragma unroll
        for (int off = 8; off >= 1; off >>= 1)
#pragma unroll
            for (int i = 0; i < 4; i++)
                mt[i] = fmaxf(mt[i], __shfl_xor_sync(0xffffffffu, mt[i], off));

#pragma unroll
        for (int i = 0; i < 4; i++) {
            float mnew = fmaxf(mrow[i], mt[i]);
            float corr = __expf(mrow[i] - mnew);
            mrow[i] = mnew;
            lrow[i] *= corr;
#pragma unroll
            for (int j = 0; j < 4; j++) O[i][j] *= corr;
            float lsum = 0.f;
#pragma unroll
            for (int j = 0; j < 4; j++) {
                float p = __expf(s[i][j] - mnew);
                s[i][j] = p;
                lsum += p;
            }
            ls[i] = lsum;
        }
#pragma unroll
        for (int off = 8; off >= 1; off >>= 1)
#pragma unroll
            for (int i = 0; i < 4; i++)
                ls[i] += __shfl_xor_sync(0xffffffffu, ls[i], off);
#pragma unroll
        for (int i = 0; i < 4; i++) lrow[i] += ls[i];

#pragma unroll
        for (int src = 0; src < 16; src++) {
            int srcLane = (lane & 16) | src;
#pragma unroll
            for (int jp = 0; jp < 4; jp++) {
                int jj = src * 4 + jp;
                float4 v4 = *reinterpret_cast<const float4*>(&Vs[jj][tx * 4]);
                float p0 = __shfl_sync(0xffffffffu, s[0][jp], srcLane);
                float p1 = __shfl_sync(0xffffffffu, s[1][jp], srcLane);
                float p2 = __shfl_sync(0xffffffffu, s[2][jp], srcLane);
                float p3 = __shfl_sync(0xffffffffu, s[3][jp], srcLane);
                O[0][0] += p0 * v4.x; O[0][1] += p0 * v4.y;
                O[0][2] += p0 * v4.z; O[0][3] += p0 * v4.w;
                O[1][0] += p1 * v4.x; O[1][1] += p1 * v4.y;
                O[1][2] += p1 * v4.z; O[1][3] += p1 * v4.w;
                O[2][0] += p2 * v4.x; O[2][1] += p2 * v4.y;
                O[2][2] += p2 * v4.z; O[2][3] += p2 * v4.w;
                O[3][0] += p3 * v4.x; O[3][1] += p3 * v4.y;
                O[3][2] += p3 * v4.z; O[3][3] += p3 * v4.w;
            }
        }
    }

    float* obase = g_attn + ((size_t)(b * S_ + qi0)) * D_ + h * DK_;
#pragma unroll
    for (int i = 0; i < 4; i++) {
        float inv = 1.0f / lrow[i];
        float4 o = make_float4(O[i][0] * inv, O[i][1] * inv,
                               O[i][2] * inv, O[i][3] * inv);
        *reinterpret_cast<float4*>(&obase[(size_t)(ty * 4 + i) * D_ + tx * 4]) = o;
    }
}

// ---------------------------------------------------------------------------
// Launch
// ---------------------------------------------------------------------------
extern "C" void kernel_launch(void* const* d_in, const int* in_sizes, int n_in,
                              void* d_out, int out_size)
{
    const float* x   = (const float*)d_in[0];
    const float* Wq  = (const float*)d_in[2];
    const float* bq  = (const float*)d_in[3];
    const float* Wk  = (const float*)d_in[4];
    const float* bk  = (const float*)d_in[5];
    const float* Wv  = (const float*)d_in[6];
    const float* bv  = (const float*)d_in[7];
    const float* Wo  = (const float*)d_in[8];
    const float* bo  = (const float*)d_in[9];
    const float* rel = (const float*)d_in[10];
    float* out = (float*)d_out;

    cudaFuncSetAttribute(gemm_tc_kernel,
                         cudaFuncAttributeMaxDynamicSharedMemorySize,
                         GEMM_SMEM_BYTES);

    // operand preparation (bf16 hi/lo splits; weights transposed)
    split_kernel<<<1024, 256>>>(x, 0, 0);
    dim3 wt(32, 8);
    dim3 wg(32, 32);
    wsplitT_kernel<<<wg, wt>>>(Wq, 0);
    wsplitT_kernel<<<wg, wt>>>(Wk, 1);
    wsplitT_kernel<<<wg, wt>>>(Wv, 2);
    wsplitT_kernel<<<wg, wt>>>(Wo, 3);

    dim3 gg(D_ / 128, MTOT / 128);   // (8, 64)
    gemm_tc_kernel<<<gg, 512, GEMM_SMEM_BYTES>>>(bq, nullptr, 0, 0, 1);  // -> g_q
    gemm_tc_kernel<<<gg, 512, GEMM_SMEM_BYTES>>>(bk, nullptr, 0, 1, 2);  // -> g_k
    gemm_tc_kernel<<<gg, 512, GEMM_SMEM_BYTES>>>(bv, nullptr, 0, 2, 3);  // -> g_v

    dim3 agrid(S_ / 64, H_, B_);
    attn_kernel<<<agrid, 256>>>(rel);                                    // -> g_attn

    split_kernel<<<1024, 256>>>(nullptr, 1, 1);                          // attn -> hi/lo
    gemm_tc_kernel<<<gg, 512, GEMM_SMEM_BYTES>>>(bo, out, 1, 3, 0);      // -> d_out
}

// round 4
// speedup vs baseline: 2.5161x; 1.4465x over previous
#include <cuda_runtime.h>
#include <cuda_bf16.h>
#include <cstdint>

#define B_ 16
#define S_ 512
#define D_ 1024
#define H_ 16
#define DK_ 64
#define MTOT (B_ * S_)   // 8192

// bf16 hi/lo scratch (alloc-free per harness rules)
__device__ __align__(16) __nv_bfloat16 g_xhi[(size_t)MTOT * D_];
__device__ __align__(16) __nv_bfloat16 g_xlo[(size_t)MTOT * D_];
__device__ __align__(16) __nv_bfloat16 g_qh[(size_t)MTOT * D_];
__device__ __align__(16) __nv_bfloat16 g_ql[(size_t)MTOT * D_];
__device__ __align__(16) __nv_bfloat16 g_kh[(size_t)MTOT * D_];
__device__ __align__(16) __nv_bfloat16 g_kl[(size_t)MTOT * D_];
__device__ __align__(16) __nv_bfloat16 g_vh[(size_t)MTOT * D_];
__device__ __align__(16) __nv_bfloat16 g_vl[(size_t)MTOT * D_];
__device__ __align__(16) __nv_bfloat16 g_ah[(size_t)MTOT * D_];
__device__ __align__(16) __nv_bfloat16 g_al[(size_t)MTOT * D_];
__device__ __align__(16) __nv_bfloat16 g_wThi[(size_t)4 * D_ * D_];
__device__ __align__(16) __nv_bfloat16 g_wTlo[(size_t)4 * D_ * D_];

// ---------------------------------------------------------------------------
// Base-PTX helpers (NO tcgen05 — unsupported at compute_103 virtual arch)
// ---------------------------------------------------------------------------
__device__ __forceinline__ uint32_t smem_to_u32(const void* p) {
    uint32_t a;
    asm("{ .reg .u64 t; cvta.to.shared.u64 t, %1; cvt.u32.u64 %0, t; }"
        : "=r"(a) : "l"(p));
    return a;
}
#define CP_ASYNC16(d, s) \
    asm volatile("cp.async.cg.shared.global [%0], [%1], 16;" :: "r"(d), "l"(s))
#define CP_COMMIT() asm volatile("cp.async.commit_group;" ::: "memory")
#define CP_WAIT1()  asm volatile("cp.async.wait_group 1;" ::: "memory")
#define CP_WAIT0()  asm volatile("cp.async.wait_group 0;" ::: "memory")

__device__ __forceinline__ void ldsm4(uint32_t* r, uint32_t a) {
    asm volatile("ldmatrix.sync.aligned.m8n8.x4.shared.b16 {%0,%1,%2,%3}, [%4];"
                 : "=r"(r[0]), "=r"(r[1]), "=r"(r[2]), "=r"(r[3]) : "r"(a));
}
__device__ __forceinline__ void ldsm4_t(uint32_t* r, uint32_t a) {
    asm volatile("ldmatrix.sync.aligned.m8n8.x4.trans.shared.b16 {%0,%1,%2,%3}, [%4];"
                 : "=r"(r[0]), "=r"(r[1]), "=r"(r[2]), "=r"(r[3]) : "r"(a));
}
__device__ __forceinline__ void mma_bf16(float* c, const uint32_t* a,
                                         const uint32_t* b) {
    asm volatile(
        "mma.sync.aligned.m16n8k16.row.col.f32.bf16.bf16.f32 "
        "{%0,%1,%2,%3}, {%4,%5,%6,%7}, {%8,%9}, {%0,%1,%2,%3};"
        : "+f"(c[0]), "+f"(c[1]), "+f"(c[2]), "+f"(c[3])
        : "r"(a[0]), "r"(a[1]), "r"(a[2]), "r"(a[3]), "r"(b[0]), "r"(b[1]));
}
// pack two fp32 -> bf16x2 (lo in low half, hi in high half)
__device__ __forceinline__ uint32_t pack_bf16x2(float lo, float hi) {
    uint32_t r;
    asm("cvt.rn.bf16x2.f32 %0, %1, %2;" : "=r"(r) : "f"(hi), "f"(lo));
    return r;
}
// FMA-only exp (MUFU-free). Valid for x <= 0, clamped at -80.
__device__ __forceinline__ float fexp(float x) {
    x = fmaxf(x, -80.f);
    float y = x * 1.4426950408889634f;
    float n = rintf(y);
    float f = y - n;
    float p = 1.3333558146428443e-3f;
    p = fmaf(p, f, 9.6181291076284771e-3f);
    p = fmaf(p, f, 5.5504108664821580e-2f);
    p = fmaf(p, f, 2.4022650695910071e-1f);
    p = fmaf(p, f, 6.9314718055994531e-1f);
    p = fmaf(p, f, 1.0f);
    return __uint_as_float(__float_as_uint(p) + (((int)n) << 23));
}

// Swizzled offset, GEMM 32-col tiles (two 64B rows per 128B phys row)
__device__ __forceinline__ uint32_t sw_off(int r, int c) {
    int p = r >> 1;
    int idx = (((r & 1) << 2) | c) ^ (p & 7);
    return (uint32_t)(p * 128 + idx * 16);
}
// Swizzled offset, attention 64-col (128B-row) tiles; c = 16B chunk 0..7
__device__ __forceinline__ uint32_t sw2(int r, int c) {
    return (uint32_t)(r * 128 + ((c ^ (r & 7)) << 4));
}

// ---------------------------------------------------------------------------
// Split fp32 x -> bf16 hi/lo
// ---------------------------------------------------------------------------
__global__ void split_kernel(const float* __restrict__ in)
{
    const int n4 = MTOT * D_ / 4;
    for (int i = blockIdx.x * blockDim.x + threadIdx.x; i < n4;
         i += gridDim.x * blockDim.x) {
        float4 v = reinterpret_cast<const float4*>(in)[i];
        uint32_t h01 = pack_bf16x2(v.x, v.y);
        uint32_t h23 = pack_bf16x2(v.z, v.w);
        float h0 = __uint_as_float(h01 << 16);
        float h1 = __uint_as_float(h01 & 0xffff0000u);
        float h2 = __uint_as_float(h23 << 16);
        float h3 = __uint_as_float(h23 & 0xffff0000u);
        reinterpret_cast<uint32_t*>(g_xhi)[i * 2 + 0] = h01;
        reinterpret_cast<uint32_t*>(g_xhi)[i * 2 + 1] = h23;
        reinterpret_cast<uint32_t*>(g_xlo)[i * 2 + 0] = pack_bf16x2(v.x - h0, v.y - h1);
        reinterpret_cast<uint32_t*>(g_xlo)[i * 2 + 1] = pack_bf16x2(v.z - h2, v.w - h3);
    }
}

// ---------------------------------------------------------------------------
// Transpose + split W [K][N] -> wT hi/lo [N][K] (bf16), slot widx
// ---------------------------------------------------------------------------
__global__ void wsplitT_kernel(const float* __restrict__ W, int widx)
{
    __shared__ float t[32][33];
    const int bx = blockIdx.x * 32;   // n tile
    const int by = blockIdx.y * 32;   // k tile
    const int tx = threadIdx.x, ty = threadIdx.y;
    for (int r = ty; r < 32; r += 8)
        t[r][tx] = W[(size_t)(by + r) * D_ + bx + tx];
    __syncthreads();
    __nv_bfloat16* hi = g_wThi + ((size_t)widx << 20);
    __nv_bfloat16* lo = g_wTlo + ((size_t)widx << 20);
    for (int r = ty; r < 32; r += 8) {
        float v = t[tx][r];                       // = W[by+tx][bx+r]
        __nv_bfloat16 h = __float2bfloat16(v);
        __nv_bfloat16 l = __float2bfloat16(v - __bfloat162float(h));
        size_t o = (size_t)(bx + r) * D_ + by + tx;
        hi[o] = h; lo[o] = l;
    }
}

// ---------------------------------------------------------------------------
// HMMA bf16x3 GEMM: C = A @ W + bias.
// csel 0: fp32 -> Cext.  csel 1/2/3: bf16 hi/lo -> (qh,ql)/(kh,kl)/(vh,vl).
// asel 0: A = x hi/lo.   asel 1: A = attn hi/lo.
// ---------------------------------------------------------------------------
#define STAGE_BYTES 32768
#define GEMM_SMEM_BYTES (2 * STAGE_BYTES)

__global__ __launch_bounds__(512, 2)
void gemm_tc_kernel(const float* __restrict__ bias, float* __restrict__ Cext,
                    int asel, int widx, int csel)
{
    extern __shared__ char smc[];
    const int tid  = threadIdx.x;
    const int lane = tid & 31;
    const int wid  = tid >> 5;
    const int wm   = wid >> 2;
    const int wn   = wid & 3;
    const int n0   = blockIdx.x * 128;
    const int m0   = blockIdx.y * 128;
    const uint32_t smem_u = smem_to_u32(smc);

    const __nv_bfloat16* Ah = ((asel == 0) ? g_xhi : g_ah) + (size_t)m0 * D_;
    const __nv_bfloat16* Al = ((asel == 0) ? g_xlo : g_al) + (size_t)m0 * D_;
    const __nv_bfloat16* Bh = g_wThi + ((size_t)widx << 20) + (size_t)n0 * D_;
    const __nv_bfloat16* Bl = g_wTlo + ((size_t)widx << 20) + (size_t)n0 * D_;

    const int lr = tid >> 2;
    const int lc = tid & 3;
    const uint32_t sdst = sw_off(lr, lc);
    const size_t gsrc = (size_t)lr * D_ + lc * 8;

    float acc[2][4][4];
#pragma unroll
    for (int i = 0; i < 2; i++)
#pragma unroll
        for (int j = 0; j < 4; j++)
#pragma unroll
            for (int k = 0; k < 4; k++) acc[i][j][k] = 0.f;

    {
        const uint32_t sb = smem_u;
        CP_ASYNC16(sb +     0 + sdst, Ah + gsrc);
        CP_ASYNC16(sb +  8192 + sdst, Al + gsrc);
        CP_ASYNC16(sb + 16384 + sdst, Bh + gsrc);
        CP_ASYNC16(sb + 24576 + sdst, Bl + gsrc);
        CP_COMMIT();
    }

#pragma unroll 1
    for (int kc = 0; kc < 32; kc++) {
        if (kc + 1 < 32) {
            const uint32_t sb = smem_u + ((kc + 1) & 1) * STAGE_BYTES;
            const size_t go = gsrc + (size_t)(kc + 1) * 32;
            CP_ASYNC16(sb +     0 + sdst, Ah + go);
            CP_ASYNC16(sb +  8192 + sdst, Al + go);
            CP_ASYNC16(sb + 16384 + sdst, Bh + go);
            CP_ASYNC16(sb + 24576 + sdst, Bl + go);
            CP_COMMIT();
            CP_WAIT1();
        } else {
            CP_WAIT0();
        }
        __syncthreads();

        const uint32_t sb = smem_u + (kc & 1) * STAGE_BYTES;
#pragma unroll
        for (int s = 0; s < 2; s++) {
            uint32_t ah[2][4], al[2][4], bh[2][4], bl[2][4];
            const int arow = wm * 32 + (lane & 15);
            const int achk = 2 * s + (lane >> 4);
            ldsm4(ah[0], sb +     0 + sw_off(arow,      achk));
            ldsm4(ah[1], sb +     0 + sw_off(arow + 16, achk));
            ldsm4(al[0], sb +  8192 + sw_off(arow,      achk));
            ldsm4(al[1], sb +  8192 + sw_off(arow + 16, achk));
            const int brow = wn * 32 + (lane & 7) + ((lane >> 4) << 3);
            const int bchk = 2 * s + ((lane >> 3) & 1);
            ldsm4(bh[0], sb + 16384 + sw_off(brow,      bchk));
            ldsm4(bh[1], sb + 16384 + sw_off(brow + 16, bchk));
            ldsm4(bl[0], sb + 24576 + sw_off(brow,      bchk));
            ldsm4(bl[1], sb + 24576 + sw_off(brow + 16, bchk));
#pragma unroll
            for (int mt = 0; mt < 2; mt++) {
#pragma unroll
                for (int nt = 0; nt < 4; nt++) {
                    const uint32_t* bhp = &bh[nt >> 1][(nt & 1) * 2];
                    const uint32_t* blp = &bl[nt >> 1][(nt & 1) * 2];
                    mma_bf16(acc[mt][nt], ah[mt], bhp);
                    mma_bf16(acc[mt][nt], ah[mt], blp);
                    mma_bf16(acc[mt][nt], al[mt], bhp);
                }
            }
        }
        __syncthreads();
    }

    // Epilogue
    if (csel == 0) {
#pragma unroll
        for (int mt = 0; mt < 2; mt++) {
            const int row = m0 + wm * 32 + mt * 16 + (lane >> 2);
#pragma unroll
            for (int nt = 0; nt < 4; nt++) {
                const int col = n0 + wn * 32 + nt * 8 + (lane & 3) * 2;
                const float bx = bias[col], by = bias[col + 1];
                float2 o0 = make_float2(acc[mt][nt][0] + bx, acc[mt][nt][1] + by);
                float2 o1 = make_float2(acc[mt][nt][2] + bx, acc[mt][nt][3] + by);
                *reinterpret_cast<float2*>(&Cext[(size_t)row * D_ + col]) = o0;
                *reinterpret_cast<float2*>(&Cext[(size_t)(row + 8) * D_ + col]) = o1;
            }
        }
    } else {
        __nv_bfloat16* Chi = (csel == 1) ? g_qh : (csel == 2) ? g_kh : g_vh;
        __nv_bfloat16* Clo = (csel == 1) ? g_ql : (csel == 2) ? g_kl : g_vl;
#pragma unroll
        for (int mt = 0; mt < 2; mt++) {
            const int row = m0 + wm * 32 + mt * 16 + (lane >> 2);
#pragma unroll
            for (int nt = 0; nt < 4; nt++) {
                const int col = n0 + wn * 32 + nt * 8 + (lane & 3) * 2;
                const float bx = bias[col], by = bias[col + 1];
#pragma unroll
                for (int half = 0; half < 2; half++) {
                    const int r = row + half * 8;
                    float v0 = acc[mt][nt][half * 2 + 0] + bx;
                    float v1 = acc[mt][nt][half * 2 + 1] + by;
                    uint32_t hv = pack_bf16x2(v0, v1);
                    float h0 = __uint_as_float(hv << 16);
                    float h1 = __uint_as_float(hv & 0xffff0000u);
                    uint32_t lv = pack_bf16x2(v0 - h0, v1 - h1);
                    *reinterpret_cast<uint32_t*>(&Chi[(size_t)r * D_ + col]) = hv;
                    *reinterpret_cast<uint32_t*>(&Clo[(size_t)r * D_ + col]) = lv;
                }
            }
        }
    }
}

// ---------------------------------------------------------------------------
// Tensor-core flash attention. CTA = 128 queries of one (b,h); 8 warps.
// QK^T and P.V via mma.sync bf16x3; FMA-only exp; rel-pos bias staged in smem.
// smem: Qh Ql Kh Kl Vh Vl (6 x 16KB) + bias (1KB) = 99328 B -> occ 1.
// ---------------------------------------------------------------------------
#define ATTN_SMEM_BYTES (6 * 16384 + 1024)

__global__ __launch_bounds__(256, 1)
void attn_tc_kernel(const float* __restrict__ rel)
{
    extern __shared__ char smc[];
    const uint32_t su = smem_to_u32(smc);
    const uint32_t sQh = su, sQl = su + 16384;
    const uint32_t sKh = su + 32768, sKl = su + 49152;
    const uint32_t sVh = su + 65536, sVl = su + 81920;
    float* bias_s = reinterpret_cast<float*>(smc + 98304);

    const int tid = threadIdx.x;
    const int lane = tid & 31;
    const int wid = tid >> 5;
    const int qt = blockIdx.x, h = blockIdx.y, b = blockIdx.z;
    const int qi0 = qt * 128;
    const int wq = wid * 16;
    const int r0l = lane >> 2;        // local row 0..7
    const int c0l = 2 * (lane & 3);   // local col pair base

    // stage Q hi/lo
#pragma unroll
    for (int i = 0; i < 4; i++) {
        const int idx = tid + i * 256;
        const int row = idx >> 3, c = idx & 7;
        const uint32_t so = sw2(row, c);
        const size_t g = (size_t)(b * S_ + qi0 + row) * D_ + h * DK_ + c * 8;
        CP_ASYNC16(sQh + so, g_qh + g);
        CP_ASYNC16(sQl + so, g_ql + g);
    }
    CP_COMMIT();
    CP_WAIT0();
    __syncthreads();

    // Q fragments (kept in registers for all 4 key tiles)
    uint32_t qh[4][4], ql[4][4];
#pragma unroll
    for (int kk = 0; kk < 4; kk++) {
        const int ar = wq + (lane & 15);
        const int ac = 2 * kk + (lane >> 4);
        ldsm4(qh[kk], sQh + sw2(ar, ac));
        ldsm4(ql[kk], sQl + sw2(ar, ac));
    }

    float Oa[8][4];
#pragma unroll
    for (int i = 0; i < 8; i++)
#pragma unroll
        for (int j = 0; j < 4; j++) Oa[i][j] = 0.f;
    float m0r = -1e30f, m1r = -1e30f, l0r = 0.f, l1r = 0.f;

#pragma unroll 1
    for (int kt = 0; kt < 4; kt++) {
        const int kj0 = kt * 128;
        __syncthreads();   // previous tile fully consumed
#pragma unroll
        for (int i = 0; i < 4; i++) {
            const int idx = tid + i * 256;
            const int row = idx >> 3, c = idx & 7;
            const uint32_t so = sw2(row, c);
            const size_t g = (size_t)(b * S_ + kj0 + row) * D_ + h * DK_ + c * 8;
            CP_ASYNC16(sKh + so, g_kh + g);
            CP_ASYNC16(sKl + so, g_kl + g);
            CP_ASYNC16(sVh + so, g_vh + g);
            CP_ASYNC16(sVl + so, g_vl + g);
        }
        {   // bias diag table: d in [0,254] used; clamp top
            const int idx = min(qi0 - kj0 + 384 + tid, 1022);
            bias_s[tid] = rel[idx * 16 + h];
        }
        CP_COMMIT();
        CP_WAIT0();
        __syncthreads();

        // ---- S = Q K^T (bf16x3) ----
        float sc[16][4];
#pragma unroll
        for (int nt = 0; nt < 16; nt++)
#pragma unroll
            for (int j = 0; j < 4; j++) sc[nt][j] = 0.f;

#pragma unroll
        for (int kk = 0; kk < 4; kk++) {
#pragma unroll
            for (int nt2 = 0; nt2 < 8; nt2++) {
                const int br = nt2 * 16 + (lane & 7) + ((lane >> 4) << 3);
                const int bc = 2 * kk + ((lane >> 3) & 1);
                const uint32_t so = sw2(br, bc);
                uint32_t kh4[4], kl4[4];
                ldsm4(kh4, sKh + so);
                ldsm4(kl4, sKl + so);
                mma_bf16(sc[2 * nt2],     qh[kk], &kh4[0]);
                mma_bf16(sc[2 * nt2],     qh[kk], &kl4[0]);
                mma_bf16(sc[2 * nt2],     ql[kk], &kh4[0]);
                mma_bf16(sc[2 * nt2 + 1], qh[kk], &kh4[2]);
                mma_bf16(sc[2 * nt2 + 1], qh[kk], &kl4[2]);
                mma_bf16(sc[2 * nt2 + 1], ql[kk], &kh4[2]);
            }
        }

        // ---- scale + bias + row max ----
        float tm0 = -1e30f, tm1 = -1e30f;
#pragma unroll
        for (int nt = 0; nt < 16; nt++) {
            const int d00 = (wq + r0l) - (nt * 8 + c0l) + 127;
            const float b00 = bias_s[d00];
            const float b01 = bias_s[d00 - 1];
            const float b10 = bias_s[d00 + 8];
            const float b11 = bias_s[d00 + 7];
            sc[nt][0] = fmaf(sc[nt][0], 0.125f, b00);
            sc[nt][1] = fmaf(sc[nt][1], 0.125f, b01);
            sc[nt][2] = fmaf(sc[nt][2], 0.125f, b10);
            sc[nt][3] = fmaf(sc[nt][3], 0.125f, b11);
            tm0 = fmaxf(tm0, fmaxf(sc[nt][0], sc[nt][1]));
            tm1 = fmaxf(tm1, fmaxf(sc[nt][2], sc[nt][3]));
        }
        tm0 = fmaxf(tm0, __shfl_xor_sync(0xffffffffu, tm0, 1));
        tm0 = fmaxf(tm0, __shfl_xor_sync(0xffffffffu, tm0, 2));
        tm1 = fmaxf(tm1, __shfl_xor_sync(0xffffffffu, tm1, 1));
        tm1 = fmaxf(tm1, __shfl_xor_sync(0xffffffffu, tm1, 2));

        const float mn0 = fmaxf(m0r, tm0), mn1 = fmaxf(m1r, tm1);
        const float cr0 = fexp(m0r - mn0), cr1 = fexp(m1r - mn1);
        m0r = mn0; m1r = mn1;
        l0r *= cr0; l1r *= cr1;
#pragma unroll
        for (int dn = 0; dn < 8; dn++) {
            Oa[dn][0] *= cr0; Oa[dn][1] *= cr0;
            Oa[dn][2] *= cr1; Oa[dn][3] *= cr1;
        }

        float ls0 = 0.f, ls1 = 0.f;
#pragma unroll
        for (int nt = 0; nt < 16; nt++) {
            sc[nt][0] = fexp(sc[nt][0] - mn0);
            sc[nt][1] = fexp(sc[nt][1] - mn0);
            sc[nt][2] = fexp(sc[nt][2] - mn1);
            sc[nt][3] = fexp(sc[nt][3] - mn1);
            ls0 += sc[nt][0] + sc[nt][1];
            ls1 += sc[nt][2] + sc[nt][3];
        }
        ls0 += __shfl_xor_sync(0xffffffffu, ls0, 1);
        ls0 += __shfl_xor_sync(0xffffffffu, ls0, 2);
        ls1 += __shfl_xor_sync(0xffffffffu, ls1, 1);
        ls1 += __shfl_xor_sync(0xffffffffu, ls1, 2);
        l0r += ls0; l1r += ls1;

        // ---- O += P V (bf16x3; P hi/lo split in registers) ----
#pragma unroll
        for (int kc = 0; kc < 8; kc++) {
            uint32_t pah[4], pal[4];
#pragma unroll
            for (int half = 0; half < 2; half++) {   // ntile 2kc / 2kc+1
                const float* p = sc[2 * kc + half];
#pragma unroll
                for (int rr = 0; rr < 2; rr++) {     // row r / r+8
                    const float p0 = p[rr * 2 + 0], p1 = p[rr * 2 + 1];
                    const uint32_t hv = pack_bf16x2(p0, p1);
                    const float h0 = __uint_as_float(hv << 16);
                    const float h1 = __uint_as_float(hv & 0xffff0000u);
                    pah[half * 2 + rr] = hv;
                    pal[half * 2 + rr] = pack_bf16x2(p0 - h0, p1 - h1);
                }
            }
#pragma unroll
            for (int dp = 0; dp < 4; dp++) {
                const int vr = kc * 16 + (lane & 15);
                const int vc = 2 * dp + (lane >> 4);
                const uint32_t so = sw2(vr, vc);
                uint32_t vh4[4], vl4[4];
                ldsm4_t(vh4, sVh + so);
                ldsm4_t(vl4, sVl + so);
                mma_bf16(Oa[2 * dp],     pah, &vh4[0]);
                mma_bf16(Oa[2 * dp],     pah, &vl4[0]);
                mma_bf16(Oa[2 * dp],     pal, &vh4[0]);
                mma_bf16(Oa[2 * dp + 1], pah, &vh4[2]);
                mma_bf16(Oa[2 * dp + 1], pah, &vl4[2]);
                mma_bf16(Oa[2 * dp + 1], pal, &vh4[2]);
            }
        }
    }

    // ---- normalize + write attn output as bf16 hi/lo ----
    const float inv0 = 1.f / l0r, inv1 = 1.f / l1r;
    const size_t row0 = (size_t)(b * S_ + qi0 + wq + r0l) * D_ + h * DK_ + c0l;
    const size_t row1 = row0 + 8 * D_;
#pragma unroll
    for (int dn = 0; dn < 8; dn++) {
        const float o00 = Oa[dn][0] * inv0, o01 = Oa[dn][1] * inv0;
        const float o10 = Oa[dn][2] * inv1, o11 = Oa[dn][3] * inv1;
        const uint32_t hv0 = pack_bf16x2(o00, o01);
        const uint32_t hv1 = pack_bf16x2(o10, o11);
        const float h00 = __uint_as_float(hv0 << 16);
        const float h01 = __uint_as_float(hv0 & 0xffff0000u);
        const float h10 = __uint_as_float(hv1 << 16);
        const float h11 = __uint_as_float(hv1 & 0xffff0000u);
        *reinterpret_cast<uint32_t*>(&g_ah[row0 + dn * 8]) = hv0;
        *reinterpret_cast<uint32_t*>(&g_ah[row1 + dn * 8]) = hv1;
        *reinterpret_cast<uint32_t*>(&g_al[row0 + dn * 8]) =
            pack_bf16x2(o00 - h00, o01 - h01);
        *reinterpret_cast<uint32_t*>(&g_al[row1 + dn * 8]) =
            pack_bf16x2(o10 - h10, o11 - h11);
    }
}

// ---------------------------------------------------------------------------
// Launch
// ---------------------------------------------------------------------------
extern "C" void kernel_launch(void* const* d_in, const int* in_sizes, int n_in,
                              void* d_out, int out_size)
{
    const float* x   = (const float*)d_in[0];
    const float* Wq  = (const float*)d_in[2];
    const float* bq  = (const float*)d_in[3];
    const float* Wk  = (const float*)d_in[4];
    const float* bk  = (const float*)d_in[5];
    const float* Wv  = (const float*)d_in[6];
    const float* bv  = (const float*)d_in[7];
    const float* Wo  = (const float*)d_in[8];
    const float* bo  = (const float*)d_in[9];
    const float* rel = (const float*)d_in[10];
    float* out = (float*)d_out;

    cudaFuncSetAttribute(gemm_tc_kernel,
                         cudaFuncAttributeMaxDynamicSharedMemorySize,
                         GEMM_SMEM_BYTES);
    cudaFuncSetAttribute(attn_tc_kernel,
                         cudaFuncAttributeMaxDynamicSharedMemorySize,
                         ATTN_SMEM_BYTES);

    split_kernel<<<1024, 256>>>(x);
    dim3 wt(32, 8);
    dim3 wg(32, 32);
    wsplitT_kernel<<<wg, wt>>>(Wq, 0);
    wsplitT_kernel<<<wg, wt>>>(Wk, 1);
    wsplitT_kernel<<<wg, wt>>>(Wv, 2);
    wsplitT_kernel<<<wg, wt>>>(Wo, 3);

    dim3 gg(D_ / 128, MTOT / 128);   // (8, 64)
    gemm_tc_kernel<<<gg, 512, GEMM_SMEM_BYTES>>>(bq, nullptr, 0, 0, 1);  // -> qh/ql
    gemm_tc_kernel<<<gg, 512, GEMM_SMEM_BYTES>>>(bk, nullptr, 0, 1, 2);  // -> kh/kl
    gemm_tc_kernel<<<gg, 512, GEMM_SMEM_BYTES>>>(bv, nullptr, 0, 2, 3);  // -> vh/vl

    dim3 agrid(S_ / 128, H_, B_);    // (4, 16, 16)
    attn_tc_kernel<<<agrid, 256, ATTN_SMEM_BYTES>>>(rel);                // -> ah/al

    gemm_tc_kernel<<<gg, 512, GEMM_SMEM_BYTES>>>(bo, out, 1, 3, 0);      // -> d_out
}

// round 5
// speedup vs baseline: 2.8877x; 1.1477x over previous
#include <cuda_runtime.h>
#include <cuda_bf16.h>
#include <cstdint>

#define B_ 16
#define S_ 512
#define D_ 1024
#define H_ 16
#define DK_ 64
#define MTOT (B_ * S_)   // 8192

// bf16 hi/lo scratch (alloc-free per harness rules)
__device__ __align__(16) __nv_bfloat16 g_xhi[(size_t)MTOT * D_];
__device__ __align__(16) __nv_bfloat16 g_xlo[(size_t)MTOT * D_];
__device__ __align__(16) __nv_bfloat16 g_qh[(size_t)MTOT * D_];
__device__ __align__(16) __nv_bfloat16 g_ql[(size_t)MTOT * D_];
__device__ __align__(16) __nv_bfloat16 g_kh[(size_t)MTOT * D_];
__device__ __align__(16) __nv_bfloat16 g_kl[(size_t)MTOT * D_];
__device__ __align__(16) __nv_bfloat16 g_vh[(size_t)MTOT * D_];
__device__ __align__(16) __nv_bfloat16 g_vl[(size_t)MTOT * D_];
__device__ __align__(16) __nv_bfloat16 g_ah[(size_t)MTOT * D_];
__device__ __align__(16) __nv_bfloat16 g_al[(size_t)MTOT * D_];
__device__ __align__(16) __nv_bfloat16 g_wThi[(size_t)4 * D_ * D_];
__device__ __align__(16) __nv_bfloat16 g_wTlo[(size_t)4 * D_ * D_];

// ---------------------------------------------------------------------------
// Base-PTX helpers (NO tcgen05 — unsupported at compute_103 virtual arch)
// ---------------------------------------------------------------------------
__device__ __forceinline__ uint32_t smem_to_u32(const void* p) {
    uint32_t a;
    asm("{ .reg .u64 t; cvta.to.shared.u64 t, %1; cvt.u32.u64 %0, t; }"
        : "=r"(a) : "l"(p));
    return a;
}
#define CP_ASYNC16(d, s) \
    asm volatile("cp.async.cg.shared.global [%0], [%1], 16;" :: "r"(d), "l"(s))
#define CP_COMMIT() asm volatile("cp.async.commit_group;" ::: "memory")
#define CP_WAIT0()  asm volatile("cp.async.wait_group 0;" ::: "memory")

__device__ __forceinline__ void ldsm4(uint32_t* r, uint32_t a) {
    asm volatile("ldmatrix.sync.aligned.m8n8.x4.shared.b16 {%0,%1,%2,%3}, [%4];"
                 : "=r"(r[0]), "=r"(r[1]), "=r"(r[2]), "=r"(r[3]) : "r"(a));
}
__device__ __forceinline__ void ldsm4_t(uint32_t* r, uint32_t a) {
    asm volatile("ldmatrix.sync.aligned.m8n8.x4.trans.shared.b16 {%0,%1,%2,%3}, [%4];"
                 : "=r"(r[0]), "=r"(r[1]), "=r"(r[2]), "=r"(r[3]) : "r"(a));
}
__device__ __forceinline__ void mma_bf16(float* c, const uint32_t* a,
                                         const uint32_t* b) {
    asm volatile(
        "mma.sync.aligned.m16n8k16.row.col.f32.bf16.bf16.f32 "
        "{%0,%1,%2,%3}, {%4,%5,%6,%7}, {%8,%9}, {%0,%1,%2,%3};"
        : "+f"(c[0]), "+f"(c[1]), "+f"(c[2]), "+f"(c[3])
        : "r"(a[0]), "r"(a[1]), "r"(a[2]), "r"(a[3]), "r"(b[0]), "r"(b[1]));
}
__device__ __forceinline__ uint32_t pack_bf16x2(float lo, float hi) {
    uint32_t r;
    asm("cvt.rn.bf16x2.f32 %0, %1, %2;" : "=r"(r) : "f"(hi), "f"(lo));
    return r;
}
// FMA-only exp (MUFU-free). Valid for x <= 0, clamped at -80.
__device__ __forceinline__ float fexp(float x) {
    x = fmaxf(x, -80.f);
    float y = x * 1.4426950408889634f;
    float n = rintf(y);
    float f = y - n;
    float p = 1.3333558146428443e-3f;
    p = fmaf(p, f, 9.6181291076284771e-3f);
    p = fmaf(p, f, 5.5504108664821580e-2f);
    p = fmaf(p, f, 2.4022650695910071e-1f);
    p = fmaf(p, f, 6.9314718055994531e-1f);
    p = fmaf(p, f, 1.0f);
    return __uint_as_float(__float_as_uint(p) + (((int)n) << 23));
}

// Swizzled offset, GEMM 32-col tiles (two 64B rows per 128B phys row)
__device__ __forceinline__ uint32_t sw_off(int r, int c) {
    int p = r >> 1;
    int idx = (((r & 1) << 2) | c) ^ (p & 7);
    return (uint32_t)(p * 128 + idx * 16);
}
// Swizzled offset, attention 64-col (128B-row) tiles; c = 16B chunk 0..7
__device__ __forceinline__ uint32_t sw2(int r, int c) {
    return (uint32_t)(r * 128 + ((c ^ (r & 7)) << 4));
}

// ---------------------------------------------------------------------------
// Split fp32 x -> bf16 hi/lo
// ---------------------------------------------------------------------------
__global__ void split_kernel(const float* __restrict__ in)
{
    const int n4 = MTOT * D_ / 4;
    for (int i = blockIdx.x * blockDim.x + threadIdx.x; i < n4;
         i += gridDim.x * blockDim.x) {
        float4 v = reinterpret_cast<const float4*>(in)[i];
        uint32_t h01 = pack_bf16x2(v.x, v.y);
        uint32_t h23 = pack_bf16x2(v.z, v.w);
        float h0 = __uint_as_float(h01 << 16);
        float h1 = __uint_as_float(h01 & 0xffff0000u);
        float h2 = __uint_as_float(h23 << 16);
        float h3 = __uint_as_float(h23 & 0xffff0000u);
        reinterpret_cast<uint32_t*>(g_xhi)[i * 2 + 0] = h01;
        reinterpret_cast<uint32_t*>(g_xhi)[i * 2 + 1] = h23;
        reinterpret_cast<uint32_t*>(g_xlo)[i * 2 + 0] = pack_bf16x2(v.x - h0, v.y - h1);
        reinterpret_cast<uint32_t*>(g_xlo)[i * 2 + 1] = pack_bf16x2(v.z - h2, v.w - h3);
    }
}

// ---------------------------------------------------------------------------
// Transpose + split all 4 weights: W [K][N] -> wT hi/lo [N][K]; z = slot
// ---------------------------------------------------------------------------
__global__ void wsplitT_kernel(const float* __restrict__ Wq,
                               const float* __restrict__ Wk,
                               const float* __restrict__ Wv,
                               const float* __restrict__ Wo)
{
    __shared__ float t[32][33];
    const int widx = blockIdx.z;
    const float* W = (widx == 0) ? Wq : (widx == 1) ? Wk : (widx == 2) ? Wv : Wo;
    const int bx = blockIdx.x * 32;   // n tile
    const int by = blockIdx.y * 32;   // k tile
    const int tx = threadIdx.x, ty = threadIdx.y;
    for (int r = ty; r < 32; r += 8)
        t[r][tx] = W[(size_t)(by + r) * D_ + bx + tx];
    __syncthreads();
    __nv_bfloat16* hi = g_wThi + ((size_t)widx << 20);
    __nv_bfloat16* lo = g_wTlo + ((size_t)widx << 20);
    for (int r = ty; r < 32; r += 8) {
        float v = t[tx][r];                       // = W[by+tx][bx+r]
        __nv_bfloat16 h = __float2bfloat16(v);
        __nv_bfloat16 l = __float2bfloat16(v - __bfloat162float(h));
        size_t o = (size_t)(bx + r) * D_ + by + tx;
        hi[o] = h; lo[o] = l;
    }
}

// ---------------------------------------------------------------------------
// Shared GEMM mainloop: acc += A(128xK) @ B(128xK)^T for this CTA's tiles.
// Single-sync 2-stage cp.async pipeline.
// ---------------------------------------------------------------------------
#define STAGE_BYTES 32768
#define GEMM_SMEM_BYTES (2 * STAGE_BYTES)

__device__ __forceinline__ void gemm_mainloop(
    uint32_t smem_u,
    const __nv_bfloat16* __restrict__ Ah, const __nv_bfloat16* __restrict__ Al,
    const __nv_bfloat16* __restrict__ Bh, const __nv_bfloat16* __restrict__ Bl,
    float acc[2][4][4])
{
    const int tid  = threadIdx.x;
    const int lane = tid & 31;
    const int wid  = tid >> 5;
    const int wm   = wid >> 2;
    const int wn   = wid & 3;
    const int lr = tid >> 2;
    const int lc = tid & 3;
    const uint32_t sdst = sw_off(lr, lc);
    const size_t gsrc = (size_t)lr * D_ + lc * 8;

    // prologue: stage 0
    CP_ASYNC16(smem_u +     0 + sdst, Ah + gsrc);
    CP_ASYNC16(smem_u +  8192 + sdst, Al + gsrc);
    CP_ASYNC16(smem_u + 16384 + sdst, Bh + gsrc);
    CP_ASYNC16(smem_u + 24576 + sdst, Bl + gsrc);
    CP_COMMIT();

#pragma unroll 1
    for (int kc = 0; kc < 32; kc++) {
        CP_WAIT0();          // stage kc&1 data arrived
        __syncthreads();     // visible to all; stage (kc+1)&1 fully consumed
        if (kc + 1 < 32) {   // prefetch overlaps the compute below
            const uint32_t sb = smem_u + ((kc + 1) & 1) * STAGE_BYTES;
            const size_t go = gsrc + (size_t)(kc + 1) * 32;
            CP_ASYNC16(sb +     0 + sdst, Ah + go);
            CP_ASYNC16(sb +  8192 + sdst, Al + go);
            CP_ASYNC16(sb + 16384 + sdst, Bh + go);
            CP_ASYNC16(sb + 24576 + sdst, Bl + go);
            CP_COMMIT();
        }

        const uint32_t sb = smem_u + (kc & 1) * STAGE_BYTES;
#pragma unroll
        for (int s = 0; s < 2; s++) {
            uint32_t ah[2][4], al[2][4], bh[2][4], bl[2][4];
            const int arow = wm * 32 + (lane & 15);
            const int achk = 2 * s + (lane >> 4);
            ldsm4(ah[0], sb +     0 + sw_off(arow,      achk));
            ldsm4(ah[1], sb +     0 + sw_off(arow + 16, achk));
            ldsm4(al[0], sb +  8192 + sw_off(arow,      achk));
            ldsm4(al[1], sb +  8192 + sw_off(arow + 16, achk));
            const int brow = wn * 32 + (lane & 7) + ((lane >> 4) << 3);
            const int bchk = 2 * s + ((lane >> 3) & 1);
            ldsm4(bh[0], sb + 16384 + sw_off(brow,      bchk));
            ldsm4(bh[1], sb + 16384 + sw_off(brow + 16, bchk));
            ldsm4(bl[0], sb + 24576 + sw_off(brow,      bchk));
            ldsm4(bl[1], sb + 24576 + sw_off(brow + 16, bchk));
#pragma unroll
            for (int mt = 0; mt < 2; mt++) {
#pragma unroll
                for (int nt = 0; nt < 4; nt++) {
                    const uint32_t* bhp = &bh[nt >> 1][(nt & 1) * 2];
                    const uint32_t* blp = &bl[nt >> 1][(nt & 1) * 2];
                    mma_bf16(acc[mt][nt], ah[mt], bhp);
                    mma_bf16(acc[mt][nt], ah[mt], blp);
                    mma_bf16(acc[mt][nt], al[mt], bhp);
                }
            }
        }
    }
}

// ---------------------------------------------------------------------------
// Fused Q/K/V projection: z selects weight slot + output; epilogue -> bf16 hi/lo
// ---------------------------------------------------------------------------
__global__ __launch_bounds__(512, 2)
void gemm_qkv_kernel(const float* __restrict__ bq,
                     const float* __restrict__ bk,
                     const float* __restrict__ bv)
{
    extern __shared__ char smc[];
    const int z = blockIdx.z;
    const int tid  = threadIdx.x;
    const int lane = tid & 31;
    const int wid  = tid >> 5;
    const int wm   = wid >> 2;
    const int wn   = wid & 3;
    const int n0   = blockIdx.x * 128;
    const int m0   = blockIdx.y * 128;

    const float* bias = (z == 0) ? bq : (z == 1) ? bk : bv;
    __nv_bfloat16* Chi = (z == 0) ? g_qh : (z == 1) ? g_kh : g_vh;
    __nv_bfloat16* Clo = (z == 0) ? g_ql : (z == 1) ? g_kl : g_vl;

    float acc[2][4][4];
#pragma unroll
    for (int i = 0; i < 2; i++)
#pragma unroll
        for (int j = 0; j < 4; j++)
#pragma unroll
            for (int k = 0; k < 4; k++) acc[i][j][k] = 0.f;

    gemm_mainloop(smem_to_u32(smc),
                  g_xhi + (size_t)m0 * D_, g_xlo + (size_t)m0 * D_,
                  g_wThi + ((size_t)z << 20) + (size_t)n0 * D_,
                  g_wTlo + ((size_t)z << 20) + (size_t)n0 * D_, acc);

#pragma unroll
    for (int mt = 0; mt < 2; mt++) {
        const int row = m0 + wm * 32 + mt * 16 + (lane >> 2);
#pragma unroll
        for (int nt = 0; nt < 4; nt++) {
            const int col = n0 + wn * 32 + nt * 8 + (lane & 3) * 2;
            const float bx = bias[col], by = bias[col + 1];
#pragma unroll
            for (int half = 0; half < 2; half++) {
                const int r = row + half * 8;
                float v0 = acc[mt][nt][half * 2 + 0] + bx;
                float v1 = acc[mt][nt][half * 2 + 1] + by;
                uint32_t hv = pack_bf16x2(v0, v1);
                float h0 = __uint_as_float(hv << 16);
                float h1 = __uint_as_float(hv & 0xffff0000u);
                uint32_t lv = pack_bf16x2(v0 - h0, v1 - h1);
                *reinterpret_cast<uint32_t*>(&Chi[(size_t)r * D_ + col]) = hv;
                *reinterpret_cast<uint32_t*>(&Clo[(size_t)r * D_ + col]) = lv;
            }
        }
    }
}

// ---------------------------------------------------------------------------
// Output projection: A = attn hi/lo, W slot 3, fp32 epilogue -> d_out
// ---------------------------------------------------------------------------
__global__ __launch_bounds__(512, 2)
void gemm_out_kernel(const float* __restrict__ bias, float* __restrict__ Cext)
{
    extern __shared__ char smc[];
    const int tid  = threadIdx.x;
    const int lane = tid & 31;
    const int wid  = tid >> 5;
    const int wm   = wid >> 2;
    const int wn   = wid & 3;
    const int n0   = blockIdx.x * 128;
    const int m0   = blockIdx.y * 128;

    float acc[2][4][4];
#pragma unroll
    for (int i = 0; i < 2; i++)
#pragma unroll
        for (int j = 0; j < 4; j++)
#pragma unroll
            for (int k = 0; k < 4; k++) acc[i][j][k] = 0.f;

    gemm_mainloop(smem_to_u32(smc),
                  g_ah + (size_t)m0 * D_, g_al + (size_t)m0 * D_,
                  g_wThi + ((size_t)3 << 20) + (size_t)n0 * D_,
                  g_wTlo + ((size_t)3 << 20) + (size_t)n0 * D_, acc);

#pragma unroll
    for (int mt = 0; mt < 2; mt++) {
        const int row = m0 + wm * 32 + mt * 16 + (lane >> 2);
#pragma unroll
        for (int nt = 0; nt < 4; nt++) {
            const int col = n0 + wn * 32 + nt * 8 + (lane & 3) * 2;
            const float bx = bias[col], by = bias[col + 1];
            float2 o0 = make_float2(acc[mt][nt][0] + bx, acc[mt][nt][1] + by);
            float2 o1 = make_float2(acc[mt][nt][2] + bx, acc[mt][nt][3] + by);
            *reinterpret_cast<float2*>(&Cext[(size_t)row * D_ + col]) = o0;
            *reinterpret_cast<float2*>(&Cext[(size_t)(row + 8) * D_ + col]) = o1;
        }
    }
}

// ---------------------------------------------------------------------------
// Tensor-core flash attention. CTA = 128 queries of one (b,h); 8 warps.
// Double-buffered K/V stages; single sync per tile; bias preloaded once.
// smem: Qh Ql (32KB) + 2 KV stages (2x64KB) + bias (2.5KB) = 162.5 KB, occ 1.
// ---------------------------------------------------------------------------
#define KV_STAGE 65536
#define ATTN_SMEM_BYTES (32768 + 2 * KV_STAGE + 2560)

__global__ __launch_bounds__(256, 1)
void attn_tc_kernel(const float* __restrict__ rel)
{
    extern __shared__ char smc[];
    const uint32_t su = smem_to_u32(smc);
    const uint32_t sQh = su, sQl = su + 16384;
    float* bias_s = reinterpret_cast<float*>(smc + 32768 + 2 * KV_STAGE);

    const int tid = threadIdx.x;
    const int lane = tid & 31;
    const int wid = tid >> 5;
    const int qt = blockIdx.x, h = blockIdx.y, b = blockIdx.z;
    const int qi0 = qt * 128;
    const int wq = wid * 16;
    const int r0l = lane >> 2;
    const int c0l = 2 * (lane & 3);

    // prologue: Q + KV stage 0 + bias table
#pragma unroll
    for (int i = 0; i < 4; i++) {
        const int idx = tid + i * 256;
        const int row = idx >> 3, c = idx & 7;
        const uint32_t so = sw2(row, c);
        const size_t g = (size_t)(b * S_ + qi0 + row) * D_ + h * DK_ + c * 8;
        CP_ASYNC16(sQh + so, g_qh + g);
        CP_ASYNC16(sQl + so, g_ql + g);
    }
    {
        const uint32_t st0 = su + 32768;
#pragma unroll
        for (int i = 0; i < 4; i++) {
            const int idx = tid + i * 256;
            const int row = idx >> 3, c = idx & 7;
            const uint32_t so = sw2(row, c);
            const size_t g = (size_t)(b * S_ + row) * D_ + h * DK_ + c * 8;
            CP_ASYNC16(st0 +     0 + so, g_kh + g);
            CP_ASYNC16(st0 + 16384 + so, g_kl + g);
            CP_ASYNC16(st0 + 32768 + so, g_vh + g);
            CP_ASYNC16(st0 + 49152 + so, g_vl + g);
        }
    }
    for (int t = tid; t < 639; t += 256)
        bias_s[t] = rel[(size_t)(qi0 + t) * H_ + h];
    CP_COMMIT();
    CP_WAIT0();
    __syncthreads();

    // Q fragments (registers, reused across all key tiles)
    uint32_t qh[4][4], ql[4][4];
#pragma unroll
    for (int kk = 0; kk < 4; kk++) {
        const int ar = wq + (lane & 15);
        const int ac = 2 * kk + (lane >> 4);
        ldsm4(qh[kk], sQh + sw2(ar, ac));
        ldsm4(ql[kk], sQl + sw2(ar, ac));
    }

    float Oa[8][4];
#pragma unroll
    for (int i = 0; i < 8; i++)
#pragma unroll
        for (int j = 0; j < 4; j++) Oa[i][j] = 0.f;
    float m0r = -1e30f, m1r = -1e30f, l0r = 0.f, l1r = 0.f;

#pragma unroll 1
    for (int kt = 0; kt < 4; kt++) {
        const int kj0 = kt * 128;
        if (kt > 0) {
            CP_WAIT0();
            __syncthreads();
        }
        if (kt + 1 < 4) {   // prefetch next KV stage; overlaps compute below
            const uint32_t st = su + 32768 + ((kt + 1) & 1) * KV_STAGE;
            const int nj0 = (kt + 1) * 128;
#pragma unroll
            for (int i = 0; i < 4; i++) {
                const int idx = tid + i * 256;
                const int row = idx >> 3, c = idx & 7;
                const uint32_t so = sw2(row, c);
                const size_t g = (size_t)(b * S_ + nj0 + row) * D_ + h * DK_ + c * 8;
                CP_ASYNC16(st +     0 + so, g_kh + g);
                CP_ASYNC16(st + 16384 + so, g_kl + g);
                CP_ASYNC16(st + 32768 + so, g_vh + g);
                CP_ASYNC16(st + 49152 + so, g_vl + g);
            }
            CP_COMMIT();
        }
        const uint32_t sKh = su + 32768 + (kt & 1) * KV_STAGE;
        const uint32_t sKl = sKh + 16384;
        const uint32_t sVh = sKh + 32768;
        const uint32_t sVl = sKh + 49152;

        // ---- S = Q K^T (bf16x3) ----
        float sc[16][4];
#pragma unroll
        for (int nt = 0; nt < 16; nt++)
#pragma unroll
            for (int j = 0; j < 4; j++) sc[nt][j] = 0.f;

#pragma unroll
        for (int kk = 0; kk < 4; kk++) {
#pragma unroll
            for (int nt2 = 0; nt2 < 8; nt2++) {
                const int br = nt2 * 16 + (lane & 7) + ((lane >> 4) << 3);
                const int bc = 2 * kk + ((lane >> 3) & 1);
                const uint32_t so = sw2(br, bc);
                uint32_t kh4[4], kl4[4];
                ldsm4(kh4, sKh + so);
                ldsm4(kl4, sKl + so);
                mma_bf16(sc[2 * nt2],     qh[kk], &kh4[0]);
                mma_bf16(sc[2 * nt2],     qh[kk], &kl4[0]);
                mma_bf16(sc[2 * nt2],     ql[kk], &kh4[0]);
                mma_bf16(sc[2 * nt2 + 1], qh[kk], &kh4[2]);
                mma_bf16(sc[2 * nt2 + 1], qh[kk], &kl4[2]);
                mma_bf16(sc[2 * nt2 + 1], ql[kk], &kh4[2]);
            }
        }

        // ---- scale + bias + row max ----
        const int dbase = 511 + wq + r0l - kj0 - c0l;
        float tm0 = -1e30f, tm1 = -1e30f;
#pragma unroll
        for (int nt = 0; nt < 16; nt++) {
            const int d00 = dbase - nt * 8;
            const float b00 = bias_s[d00];
            const float b01 = bias_s[d00 - 1];
            const float b10 = bias_s[d00 + 8];
            const float b11 = bias_s[d00 + 7];
            sc[nt][0] = fmaf(sc[nt][0], 0.125f, b00);
            sc[nt][1] = fmaf(sc[nt][1], 0.125f, b01);
            sc[nt][2] = fmaf(sc[nt][2], 0.125f, b10);
            sc[nt][3] = fmaf(sc[nt][3], 0.125f, b11);
            tm0 = fmaxf(tm0, fmaxf(sc[nt][0], sc[nt][1]));
            tm1 = fmaxf(tm1, fmaxf(sc[nt][2], sc[nt][3]));
        }
        tm0 = fmaxf(tm0, __shfl_xor_sync(0xffffffffu, tm0, 1));
        tm0 = fmaxf(tm0, __shfl_xor_sync(0xffffffffu, tm0, 2));
        tm1 = fmaxf(tm1, __shfl_xor_sync(0xffffffffu, tm1, 1));
        tm1 = fmaxf(tm1, __shfl_xor_sync(0xffffffffu, tm1, 2));

        const float mn0 = fmaxf(m0r, tm0), mn1 = fmaxf(m1r, tm1);
        const float cr0 = fexp(m0r - mn0), cr1 = fexp(m1r - mn1);
        m0r = mn0; m1r = mn1;
        l0r *= cr0; l1r *= cr1;
#pragma unroll
        for (int dn = 0; dn < 8; dn++) {
            Oa[dn][0] *= cr0; Oa[dn][1] *= cr0;
            Oa[dn][2] *= cr1; Oa[dn][3] *= cr1;
        }

        float ls0 = 0.f, ls1 = 0.f;
#pragma unroll
        for (int nt = 0; nt < 16; nt++) {
            sc[nt][0] = fexp(sc[nt][0] - mn0);
            sc[nt][1] = fexp(sc[nt][1] - mn0);
            sc[nt][2] = fexp(sc[nt][2] - mn1);
            sc[nt][3] = fexp(sc[nt][3] - mn1);
            ls0 += sc[nt][0] + sc[nt][1];
            ls1 += sc[nt][2] + sc[nt][3];
        }
        ls0 += __shfl_xor_sync(0xffffffffu, ls0, 1);
        ls0 += __shfl_xor_sync(0xffffffffu, ls0, 2);
        ls1 += __shfl_xor_sync(0xffffffffu, ls1, 1);
        ls1 += __shfl_xor_sync(0xffffffffu, ls1, 2);
        l0r += ls0; l1r += ls1;

        // ---- O += P V (bf16x3; P hi/lo split in registers) ----
#pragma unroll
        for (int kc = 0; kc < 8; kc++) {
            uint32_t pah[4], pal[4];
#pragma unroll
            for (int half = 0; half < 2; half++) {
                const float* p = sc[2 * kc + half];
#pragma unroll
                for (int rr = 0; rr < 2; rr++) {
                    const float p0 = p[rr * 2 + 0], p1 = p[rr * 2 + 1];
                    const uint32_t hv = pack_bf16x2(p0, p1);
                    const float h0 = __uint_as_float(hv << 16);
                    const float h1 = __uint_as_float(hv & 0xffff0000u);
                    pah[half * 2 + rr] = hv;
                    pal[half * 2 + rr] = pack_bf16x2(p0 - h0, p1 - h1);
                }
            }
#pragma unroll
            for (int dp = 0; dp < 4; dp++) {
                const int vr = kc * 16 + (lane & 15);
                const int vc = 2 * dp + (lane >> 4);
                const uint32_t so = sw2(vr, vc);
                uint32_t vh4[4], vl4[4];
                ldsm4_t(vh4, sVh + so);
                ldsm4_t(vl4, sVl + so);
                mma_bf16(Oa[2 * dp],     pah, &vh4[0]);
                mma_bf16(Oa[2 * dp],     pah, &vl4[0]);
                mma_bf16(Oa[2 * dp],     pal, &vh4[0]);
                mma_bf16(Oa[2 * dp + 1], pah, &vh4[2]);
                mma_bf16(Oa[2 * dp + 1], pah, &vl4[2]);
                mma_bf16(Oa[2 * dp + 1], pal, &vh4[2]);
            }
        }
    }

    // ---- normalize + write attn output as bf16 hi/lo ----
    const float inv0 = 1.f / l0r, inv1 = 1.f / l1r;
    const size_t row0 = (size_t)(b * S_ + qi0 + wq + r0l) * D_ + h * DK_ + c0l;
    const size_t row1 = row0 + 8 * D_;
#pragma unroll
    for (int dn = 0; dn < 8; dn++) {
        const float o00 = Oa[dn][0] * inv0, o01 = Oa[dn][1] * inv0;
        const float o10 = Oa[dn][2] * inv1, o11 = Oa[dn][3] * inv1;
        const uint32_t hv0 = pack_bf16x2(o00, o01);
        const uint32_t hv1 = pack_bf16x2(o10, o11);
        const float h00 = __uint_as_float(hv0 << 16);
        const float h01 = __uint_as_float(hv0 & 0xffff0000u);
        const float h10 = __uint_as_float(hv1 << 16);
        const float h11 = __uint_as_float(hv1 & 0xffff0000u);
        *reinterpret_cast<uint32_t*>(&g_ah[row0 + dn * 8]) = hv0;
        *reinterpret_cast<uint32_t*>(&g_ah[row1 + dn * 8]) = hv1;
        *reinterpret_cast<uint32_t*>(&g_al[row0 + dn * 8]) =
            pack_bf16x2(o00 - h00, o01 - h01);
        *reinterpret_cast<uint32_t*>(&g_al[row1 + dn * 8]) =
            pack_bf16x2(o10 - h10, o11 - h11);
    }
}

// ---------------------------------------------------------------------------
// Launch
// ---------------------------------------------------------------------------
extern "C" void kernel_launch(void* const* d_in, const int* in_sizes, int n_in,
                              void* d_out, int out_size)
{
    const float* x   = (const float*)d_in[0];
    const float* Wq  = (const float*)d_in[2];
    const float* bq  = (const float*)d_in[3];
    const float* Wk  = (const float*)d_in[4];
    const float* bk  = (const float*)d_in[5];
    const float* Wv  = (const float*)d_in[6];
    const float* bv  = (const float*)d_in[7];
    const float* Wo  = (const float*)d_in[8];
    const float* bo  = (const float*)d_in[9];
    const float* rel = (const float*)d_in[10];
    float* out = (float*)d_out;

    cudaFuncSetAttribute(gemm_qkv_kernel,
                         cudaFuncAttributeMaxDynamicSharedMemorySize,
                         GEMM_SMEM_BYTES);
    cudaFuncSetAttribute(gemm_out_kernel,
                         cudaFuncAttributeMaxDynamicSharedMemorySize,
                         GEMM_SMEM_BYTES);
    cudaFuncSetAttribute(attn_tc_kernel,
                         cudaFuncAttributeMaxDynamicSharedMemorySize,
                         ATTN_SMEM_BYTES);

    split_kernel<<<1024, 256>>>(x);
    dim3 wt(32, 8);
    dim3 wg(32, 32, 4);
    wsplitT_kernel<<<wg, wt>>>(Wq, Wk, Wv, Wo);

    dim3 gq(D_ / 128, MTOT / 128, 3);   // (8, 64, 3)
    gemm_qkv_kernel<<<gq, 512, GEMM_SMEM_BYTES>>>(bq, bk, bv);   // -> q/k/v hi,lo

    dim3 agrid(S_ / 128, H_, B_);       // (4, 16, 16)
    attn_tc_kernel<<<agrid, 256, ATTN_SMEM_BYTES>>>(rel);        // -> ah/al

    dim3 gg(D_ / 128, MTOT / 128);      // (8, 64)
    gemm_out_kernel<<<gg, 512, GEMM_SMEM_BYTES>>>(bo, out);      // -> d_out
}

// round 6
// speedup vs baseline: 3.0707x; 1.0634x over previous
#include <cuda_runtime.h>
#include <cuda_bf16.h>
#include <cstdint>

#define B_ 16
#define S_ 512
#define D_ 1024
#define H_ 16
#define DK_ 64
#define MTOT (B_ * S_)   // 8192

// bf16 hi/lo scratch (alloc-free per harness rules)
__device__ __align__(16) __nv_bfloat16 g_xhi[(size_t)MTOT * D_];
__device__ __align__(16) __nv_bfloat16 g_xlo[(size_t)MTOT * D_];
__device__ __align__(16) __nv_bfloat16 g_qh[(size_t)MTOT * D_];
__device__ __align__(16) __nv_bfloat16 g_ql[(size_t)MTOT * D_];
__device__ __align__(16) __nv_bfloat16 g_kh[(size_t)MTOT * D_];
__device__ __align__(16) __nv_bfloat16 g_kl[(size_t)MTOT * D_];
__device__ __align__(16) __nv_bfloat16 g_vh[(size_t)MTOT * D_];
__device__ __align__(16) __nv_bfloat16 g_vl[(size_t)MTOT * D_];
__device__ __align__(16) __nv_bfloat16 g_ah[(size_t)MTOT * D_];
__device__ __align__(16) __nv_bfloat16 g_al[(size_t)MTOT * D_];
__device__ __align__(16) __nv_bfloat16 g_wThi[(size_t)4 * D_ * D_];
__device__ __align__(16) __nv_bfloat16 g_wTlo[(size_t)4 * D_ * D_];

// ---------------------------------------------------------------------------
// Base-PTX helpers (NO tcgen05 — unsupported at compute_103 virtual arch)
// ---------------------------------------------------------------------------
__device__ __forceinline__ uint32_t smem_to_u32(const void* p) {
    uint32_t a;
    asm("{ .reg .u64 t; cvta.to.shared.u64 t, %1; cvt.u32.u64 %0, t; }"
        : "=r"(a) : "l"(p));
    return a;
}
#define CP_ASYNC16(d, s) \
    asm volatile("cp.async.cg.shared.global [%0], [%1], 16;" :: "r"(d), "l"(s))
#define CP_COMMIT() asm volatile("cp.async.commit_group;" ::: "memory")
#define CP_WAIT0()  asm volatile("cp.async.wait_group 0;" ::: "memory")

__device__ __forceinline__ void ldsm4(uint32_t* r, uint32_t a) {
    asm volatile("ldmatrix.sync.aligned.m8n8.x4.shared.b16 {%0,%1,%2,%3}, [%4];"
                 : "=r"(r[0]), "=r"(r[1]), "=r"(r[2]), "=r"(r[3]) : "r"(a));
}
__device__ __forceinline__ void ldsm4_t(uint32_t* r, uint32_t a) {
    asm volatile("ldmatrix.sync.aligned.m8n8.x4.trans.shared.b16 {%0,%1,%2,%3}, [%4];"
                 : "=r"(r[0]), "=r"(r[1]), "=r"(r[2]), "=r"(r[3]) : "r"(a));
}
__device__ __forceinline__ void mma_bf16(float* c, const uint32_t* a,
                                         const uint32_t* b) {
    asm volatile(
        "mma.sync.aligned.m16n8k16.row.col.f32.bf16.bf16.f32 "
        "{%0,%1,%2,%3}, {%4,%5,%6,%7}, {%8,%9}, {%0,%1,%2,%3};"
        : "+f"(c[0]), "+f"(c[1]), "+f"(c[2]), "+f"(c[3])
        : "r"(a[0]), "r"(a[1]), "r"(a[2]), "r"(a[3]), "r"(b[0]), "r"(b[1]));
}
__device__ __forceinline__ uint32_t pack_bf16x2(float lo, float hi) {
    uint32_t r;
    asm("cvt.rn.bf16x2.f32 %0, %1, %2;" : "=r"(r) : "f"(hi), "f"(lo));
    return r;
}
// FMA-only exp (MUFU-free). Valid for x <= 0, clamped at -80.
__device__ __forceinline__ float fexp(float x) {
    x = fmaxf(x, -80.f);
    float y = x * 1.4426950408889634f;
    float n = rintf(y);
    float f = y - n;
    float p = 1.3333558146428443e-3f;
    p = fmaf(p, f, 9.6181291076284771e-3f);
    p = fmaf(p, f, 5.5504108664821580e-2f);
    p = fmaf(p, f, 2.4022650695910071e-1f);
    p = fmaf(p, f, 6.9314718055994531e-1f);
    p = fmaf(p, f, 1.0f);
    return __uint_as_float(__float_as_uint(p) + (((int)n) << 23));
}

// Swizzled offset, GEMM 32-col tiles (two 64B rows per 128B phys row)
__device__ __forceinline__ uint32_t sw_off(int r, int c) {
    int p = r >> 1;
    int idx = (((r & 1) << 2) | c) ^ (p & 7);
    return (uint32_t)(p * 128 + idx * 16);
}
// Swizzled offset, attention 64-col (128B-row) tiles; c = 16B chunk 0..7
__device__ __forceinline__ uint32_t sw2(int r, int c) {
    return (uint32_t)(r * 128 + ((c ^ (r & 7)) << 4));
}

// ---------------------------------------------------------------------------
// Split fp32 x -> bf16 hi/lo
// ---------------------------------------------------------------------------
__global__ void split_kernel(const float* __restrict__ in)
{
    const int n4 = MTOT * D_ / 4;
    for (int i = blockIdx.x * blockDim.x + threadIdx.x; i < n4;
         i += gridDim.x * blockDim.x) {
        float4 v = reinterpret_cast<const float4*>(in)[i];
        uint32_t h01 = pack_bf16x2(v.x, v.y);
        uint32_t h23 = pack_bf16x2(v.z, v.w);
        float h0 = __uint_as_float(h01 << 16);
        float h1 = __uint_as_float(h01 & 0xffff0000u);
        float h2 = __uint_as_float(h23 << 16);
        float h3 = __uint_as_float(h23 & 0xffff0000u);
        reinterpret_cast<uint32_t*>(g_xhi)[i * 2 + 0] = h01;
        reinterpret_cast<uint32_t*>(g_xhi)[i * 2 + 1] = h23;
        reinterpret_cast<uint32_t*>(g_xlo)[i * 2 + 0] = pack_bf16x2(v.x - h0, v.y - h1);
        reinterpret_cast<uint32_t*>(g_xlo)[i * 2 + 1] = pack_bf16x2(v.z - h2, v.w - h3);
    }
}

// ---------------------------------------------------------------------------
// Transpose + split all 4 weights: W [K][N] -> wT hi/lo [N][K]; z = slot
// ---------------------------------------------------------------------------
__global__ void wsplitT_kernel(const float* __restrict__ Wq,
                               const float* __restrict__ Wk,
                               const float* __restrict__ Wv,
                               const float* __restrict__ Wo)
{
    __shared__ float t[32][33];
    const int widx = blockIdx.z;
    const float* W = (widx == 0) ? Wq : (widx == 1) ? Wk : (widx == 2) ? Wv : Wo;
    const int bx = blockIdx.x * 32;   // n tile
    const int by = blockIdx.y * 32;   // k tile
    const int tx = threadIdx.x, ty = threadIdx.y;
    for (int r = ty; r < 32; r += 8)
        t[r][tx] = W[(size_t)(by + r) * D_ + bx + tx];
    __syncthreads();
    __nv_bfloat16* hi = g_wThi + ((size_t)widx << 20);
    __nv_bfloat16* lo = g_wTlo + ((size_t)widx << 20);
    for (int r = ty; r < 32; r += 8) {
        float v = t[tx][r];                       // = W[by+tx][bx+r]
        __nv_bfloat16 h = __float2bfloat16(v);
        __nv_bfloat16 l = __float2bfloat16(v - __bfloat162float(h));
        size_t o = (size_t)(bx + r) * D_ + by + tx;
        hi[o] = h; lo[o] = l;
    }
}

// ---------------------------------------------------------------------------
// Shared GEMM mainloop: 256 threads, 8 warps (2x4), warp tile 64x32.
// Single-sync 2-stage cp.async pipeline; no register spills (<=128 live).
// ---------------------------------------------------------------------------
#define STAGE_BYTES 32768
#define GEMM_SMEM_BYTES (2 * STAGE_BYTES)

__device__ __forceinline__ void gemm_mainloop(
    uint32_t smem_u,
    const __nv_bfloat16* __restrict__ Ah, const __nv_bfloat16* __restrict__ Al,
    const __nv_bfloat16* __restrict__ Bh, const __nv_bfloat16* __restrict__ Bl,
    float acc[4][4][4])
{
    const int tid  = threadIdx.x;
    const int lane = tid & 31;
    const int wid  = tid >> 5;
    const int wm   = wid >> 2;          // 0..1 (64-row slab)
    const int wn   = wid & 3;           // 0..3 (32-col slab)

    // cp.async mapping: 256 threads cover 512 16B chunks per 8KB tile in 2 steps
    const int lr0 = tid >> 2;           // rows 0..63
    const int lc  = tid & 3;
    const uint32_t sd0 = sw_off(lr0,      lc);
    const uint32_t sd1 = sw_off(lr0 + 64, lc);
    const size_t g0 = (size_t)lr0 * D_ + lc * 8;
    const size_t g1 = (size_t)(lr0 + 64) * D_ + lc * 8;

    // prologue: stage 0
    CP_ASYNC16(smem_u +     0 + sd0, Ah + g0);
    CP_ASYNC16(smem_u +     0 + sd1, Ah + g1);
    CP_ASYNC16(smem_u +  8192 + sd0, Al + g0);
    CP_ASYNC16(smem_u +  8192 + sd1, Al + g1);
    CP_ASYNC16(smem_u + 16384 + sd0, Bh + g0);
    CP_ASYNC16(smem_u + 16384 + sd1, Bh + g1);
    CP_ASYNC16(smem_u + 24576 + sd0, Bl + g0);
    CP_ASYNC16(smem_u + 24576 + sd1, Bl + g1);
    CP_COMMIT();

#pragma unroll 1
    for (int kc = 0; kc < 32; kc++) {
        CP_WAIT0();          // stage kc&1 arrived
        __syncthreads();     // stage (kc+1)&1 fully consumed by all warps
        if (kc + 1 < 32) {   // prefetch overlaps the compute below
            const uint32_t sb = smem_u + ((kc + 1) & 1) * STAGE_BYTES;
            const size_t o0 = g0 + (size_t)(kc + 1) * 32;
            const size_t o1 = g1 + (size_t)(kc + 1) * 32;
            CP_ASYNC16(sb +     0 + sd0, Ah + o0);
            CP_ASYNC16(sb +     0 + sd1, Ah + o1);
            CP_ASYNC16(sb +  8192 + sd0, Al + o0);
            CP_ASYNC16(sb +  8192 + sd1, Al + o1);
            CP_ASYNC16(sb + 16384 + sd0, Bh + o0);
            CP_ASYNC16(sb + 16384 + sd1, Bh + o1);
            CP_ASYNC16(sb + 24576 + sd0, Bl + o0);
            CP_ASYNC16(sb + 24576 + sd1, Bl + o1);
            CP_COMMIT();
        }

        const uint32_t sb = smem_u + (kc & 1) * STAGE_BYTES;
#pragma unroll
        for (int s = 0; s < 2; s++) {
            uint32_t ah[4][4], al[4][4], bh[2][4], bl[2][4];
            const int achk = 2 * s + (lane >> 4);
#pragma unroll
            for (int mt = 0; mt < 4; mt++) {
                const int arow = wm * 64 + mt * 16 + (lane & 15);
                ldsm4(ah[mt], sb +    0 + sw_off(arow, achk));
                ldsm4(al[mt], sb + 8192 + sw_off(arow, achk));
            }
            const int bchk = 2 * s + ((lane >> 3) & 1);
#pragma unroll
            for (int bn = 0; bn < 2; bn++) {
                const int brow = wn * 32 + bn * 16 + (lane & 7) + ((lane >> 4) << 3);
                ldsm4(bh[bn], sb + 16384 + sw_off(brow, bchk));
                ldsm4(bl[bn], sb + 24576 + sw_off(brow, bchk));
            }
#pragma unroll
            for (int mt = 0; mt < 4; mt++) {
#pragma unroll
                for (int nt = 0; nt < 4; nt++) {
                    const uint32_t* bhp = &bh[nt >> 1][(nt & 1) * 2];
                    const uint32_t* blp = &bl[nt >> 1][(nt & 1) * 2];
                    mma_bf16(acc[mt][nt], ah[mt], bhp);
                    mma_bf16(acc[mt][nt], ah[mt], blp);
                    mma_bf16(acc[mt][nt], al[mt], bhp);
                }
            }
        }
    }
}

// ---------------------------------------------------------------------------
// Fused Q/K/V projection: z selects weight slot + output; epilogue -> bf16 hi/lo
// ---------------------------------------------------------------------------
__global__ __launch_bounds__(256, 2)
void gemm_qkv_kernel(const float* __restrict__ bq,
                     const float* __restrict__ bk,
                     const float* __restrict__ bv)
{
    extern __shared__ char smc[];
    const int z = blockIdx.z;
    const int tid  = threadIdx.x;
    const int lane = tid & 31;
    const int wid  = tid >> 5;
    const int wm   = wid >> 2;
    const int wn   = wid & 3;
    const int n0   = blockIdx.x * 128;
    const int m0   = blockIdx.y * 128;

    const float* bias = (z == 0) ? bq : (z == 1) ? bk : bv;
    __nv_bfloat16* Chi = (z == 0) ? g_qh : (z == 1) ? g_kh : g_vh;
    __nv_bfloat16* Clo = (z == 0) ? g_ql : (z == 1) ? g_kl : g_vl;

    float acc[4][4][4];
#pragma unroll
    for (int i = 0; i < 4; i++)
#pragma unroll
        for (int j = 0; j < 4; j++)
#pragma unroll
            for (int k = 0; k < 4; k++) acc[i][j][k] = 0.f;

    gemm_mainloop(smem_to_u32(smc),
                  g_xhi + (size_t)m0 * D_, g_xlo + (size_t)m0 * D_,
                  g_wThi + ((size_t)z << 20) + (size_t)n0 * D_,
                  g_wTlo + ((size_t)z << 20) + (size_t)n0 * D_, acc);

#pragma unroll
    for (int mt = 0; mt < 4; mt++) {
        const int row = m0 + wm * 64 + mt * 16 + (lane >> 2);
#pragma unroll
        for (int nt = 0; nt < 4; nt++) {
            const int col = n0 + wn * 32 + nt * 8 + (lane & 3) * 2;
            const float bx = bias[col], by = bias[col + 1];
#pragma unroll
            for (int half = 0; half < 2; half++) {
                const int r = row + half * 8;
                float v0 = acc[mt][nt][half * 2 + 0] + bx;
                float v1 = acc[mt][nt][half * 2 + 1] + by;
                uint32_t hv = pack_bf16x2(v0, v1);
                float h0 = __uint_as_float(hv << 16);
                float h1 = __uint_as_float(hv & 0xffff0000u);
                uint32_t lv = pack_bf16x2(v0 - h0, v1 - h1);
                *reinterpret_cast<uint32_t*>(&Chi[(size_t)r * D_ + col]) = hv;
                *reinterpret_cast<uint32_t*>(&Clo[(size_t)r * D_ + col]) = lv;
            }
        }
    }
}

// ---------------------------------------------------------------------------
// Output projection: A = attn hi/lo, W slot 3, fp32 epilogue -> d_out
// ---------------------------------------------------------------------------
__global__ __launch_bounds__(256, 2)
void gemm_out_kernel(const float* __restrict__ bias, float* __restrict__ Cext)
{
    extern __shared__ char smc[];
    const int tid  = threadIdx.x;
    const int lane = tid & 31;
    const int wid  = tid >> 5;
    const int wm   = wid >> 2;
    const int wn   = wid & 3;
    const int n0   = blockIdx.x * 128;
    const int m0   = blockIdx.y * 128;

    float acc[4][4][4];
#pragma unroll
    for (int i = 0; i < 4; i++)
#pragma unroll
        for (int j = 0; j < 4; j++)
#pragma unroll
            for (int k = 0; k < 4; k++) acc[i][j][k] = 0.f;

    gemm_mainloop(smem_to_u32(smc),
                  g_ah + (size_t)m0 * D_, g_al + (size_t)m0 * D_,
                  g_wThi + ((size_t)3 << 20) + (size_t)n0 * D_,
                  g_wTlo + ((size_t)3 << 20) + (size_t)n0 * D_, acc);

#pragma unroll
    for (int mt = 0; mt < 4; mt++) {
        const int row = m0 + wm * 64 + mt * 16 + (lane >> 2);
#pragma unroll
        for (int nt = 0; nt < 4; nt++) {
            const int col = n0 + wn * 32 + nt * 8 + (lane & 3) * 2;
            const float bx = bias[col], by = bias[col + 1];
            float2 o0 = make_float2(acc[mt][nt][0] + bx, acc[mt][nt][1] + by);
            float2 o1 = make_float2(acc[mt][nt][2] + bx, acc[mt][nt][3] + by);
            *reinterpret_cast<float2*>(&Cext[(size_t)row * D_ + col]) = o0;
            *reinterpret_cast<float2*>(&Cext[(size_t)(row + 8) * D_ + col]) = o1;
        }
    }
}

// ---------------------------------------------------------------------------
// Tensor-core flash attention (unchanged from round 5: 155us).
// ---------------------------------------------------------------------------
#define KV_STAGE 65536
#define ATTN_SMEM_BYTES (32768 + 2 * KV_STAGE + 2560)

__global__ __launch_bounds__(256, 1)
void attn_tc_kernel(const float* __restrict__ rel)
{
    extern __shared__ char smc[];
    const uint32_t su = smem_to_u32(smc);
    const uint32_t sQh = su, sQl = su + 16384;
    float* bias_s = reinterpret_cast<float*>(smc + 32768 + 2 * KV_STAGE);

    const int tid = threadIdx.x;
    const int lane = tid & 31;
    const int wid = tid >> 5;
    const int qt = blockIdx.x, h = blockIdx.y, b = blockIdx.z;
    const int qi0 = qt * 128;
    const int wq = wid * 16;
    const int r0l = lane >> 2;
    const int c0l = 2 * (lane & 3);

    // prologue: Q + KV stage 0 + bias table
#pragma unroll
    for (int i = 0; i < 4; i++) {
        const int idx = tid + i * 256;
        const int row = idx >> 3, c = idx & 7;
        const uint32_t so = sw2(row, c);
        const size_t g = (size_t)(b * S_ + qi0 + row) * D_ + h * DK_ + c * 8;
        CP_ASYNC16(sQh + so, g_qh + g);
        CP_ASYNC16(sQl + so, g_ql + g);
    }
    {
        const uint32_t st0 = su + 32768;
#pragma unroll
        for (int i = 0; i < 4; i++) {
            const int idx = tid + i * 256;
            const int row = idx >> 3, c = idx & 7;
            const uint32_t so = sw2(row, c);
            const size_t g = (size_t)(b * S_ + row) * D_ + h * DK_ + c * 8;
            CP_ASYNC16(st0 +     0 + so, g_kh + g);
            CP_ASYNC16(st0 + 16384 + so, g_kl + g);
            CP_ASYNC16(st0 + 32768 + so, g_vh + g);
            CP_ASYNC16(st0 + 49152 + so, g_vl + g);
        }
    }
    for (int t = tid; t < 639; t += 256)
        bias_s[t] = rel[(size_t)(qi0 + t) * H_ + h];
    CP_COMMIT();
    CP_WAIT0();
    __syncthreads();

    uint32_t qh[4][4], ql[4][4];
#pragma unroll
    for (int kk = 0; kk < 4; kk++) {
        const int ar = wq + (lane & 15);
        const int ac = 2 * kk + (lane >> 4);
        ldsm4(qh[kk], sQh + sw2(ar, ac));
        ldsm4(ql[kk], sQl + sw2(ar, ac));
    }

    float Oa[8][4];
#pragma unroll
    for (int i = 0; i < 8; i++)
#pragma unroll
        for (int j = 0; j < 4; j++) Oa[i][j] = 0.f;
    float m0r = -1e30f, m1r = -1e30f, l0r = 0.f, l1r = 0.f;

#pragma unroll 1
    for (int kt = 0; kt < 4; kt++) {
        const int kj0 = kt * 128;
        if (kt > 0) {
            CP_WAIT0();
            __syncthreads();
        }
        if (kt + 1 < 4) {
            const uint32_t st = su + 32768 + ((kt + 1) & 1) * KV_STAGE;
            const int nj0 = (kt + 1) * 128;
#pragma unroll
            for (int i = 0; i < 4; i++) {
                const int idx = tid + i * 256;
                const int row = idx >> 3, c = idx & 7;
                const uint32_t so = sw2(row, c);
                const size_t g = (size_t)(b * S_ + nj0 + row) * D_ + h * DK_ + c * 8;
                CP_ASYNC16(st +     0 + so, g_kh + g);
                CP_ASYNC16(st + 16384 + so, g_kl + g);
                CP_ASYNC16(st + 32768 + so, g_vh + g);
                CP_ASYNC16(st + 49152 + so, g_vl + g);
            }
            CP_COMMIT();
        }
        const uint32_t sKh = su + 32768 + (kt & 1) * KV_STAGE;
        const uint32_t sKl = sKh + 16384;
        const uint32_t sVh = sKh + 32768;
        const uint32_t sVl = sKh + 49152;

        float sc[16][4];
#pragma unroll
        for (int nt = 0; nt < 16; nt++)
#pragma unroll
            for (int j = 0; j < 4; j++) sc[nt][j] = 0.f;

#pragma unroll
        for (int kk = 0; kk < 4; kk++) {
#pragma unroll
            for (int nt2 = 0; nt2 < 8; nt2++) {
                const int br = nt2 * 16 + (lane & 7) + ((lane >> 4) << 3);
                const int bc = 2 * kk + ((lane >> 3) & 1);
                const uint32_t so = sw2(br, bc);
                uint32_t kh4[4], kl4[4];
                ldsm4(kh4, sKh + so);
                ldsm4(kl4, sKl + so);
                mma_bf16(sc[2 * nt2],     qh[kk], &kh4[0]);
                mma_bf16(sc[2 * nt2],     qh[kk], &kl4[0]);
                mma_bf16(sc[2 * nt2],     ql[kk], &kh4[0]);
                mma_bf16(sc[2 * nt2 + 1], qh[kk], &kh4[2]);
                mma_bf16(sc[2 * nt2 + 1], qh[kk], &kl4[2]);
                mma_bf16(sc[2 * nt2 + 1], ql[kk], &kh4[2]);
            }
        }

        const int dbase = 511 + wq + r0l - kj0 - c0l;
        float tm0 = -1e30f, tm1 = -1e30f;
#pragma unroll
        for (int nt = 0; nt < 16; nt++) {
            const int d00 = dbase - nt * 8;
            const float b00 = bias_s[d00];
            const float b01 = bias_s[d00 - 1];
            const float b10 = bias_s[d00 + 8];
            const float b11 = bias_s[d00 + 7];
            sc[nt][0] = fmaf(sc[nt][0], 0.125f, b00);
            sc[nt][1] = fmaf(sc[nt][1], 0.125f, b01);
            sc[nt][2] = fmaf(sc[nt][2], 0.125f, b10);
            sc[nt][3] = fmaf(sc[nt][3], 0.125f, b11);
            tm0 = fmaxf(tm0, fmaxf(sc[nt][0], sc[nt][1]));
            tm1 = fmaxf(tm1, fmaxf(sc[nt][2], sc[nt][3]));
        }
        tm0 = fmaxf(tm0, __shfl_xor_sync(0xffffffffu, tm0, 1));
        tm0 = fmaxf(tm0, __shfl_xor_sync(0xffffffffu, tm0, 2));
        tm1 = fmaxf(tm1, __shfl_xor_sync(0xffffffffu, tm1, 1));
        tm1 = fmaxf(tm1, __shfl_xor_sync(0xffffffffu, tm1, 2));

        const float mn0 = fmaxf(m0r, tm0), mn1 = fmaxf(m1r, tm1);
        const float cr0 = fexp(m0r - mn0), cr1 = fexp(m1r - mn1);
        m0r = mn0; m1r = mn1;
        l0r *= cr0; l1r *= cr1;
#pragma unroll
        for (int dn = 0; dn < 8; dn++) {
            Oa[dn][0] *= cr0; Oa[dn][1] *= cr0;
            Oa[dn][2] *= cr1; Oa[dn][3] *= cr1;
        }

        float ls0 = 0.f, ls1 = 0.f;
#pragma unroll
        for (int nt = 0; nt < 16; nt++) {
            sc[nt][0] = fexp(sc[nt][0] - mn0);
            sc[nt][1] = fexp(sc[nt][1] - mn0);
            sc[nt][2] = fexp(sc[nt][2] - mn1);
            sc[nt][3] = fexp(sc[nt][3] - mn1);
            ls0 += sc[nt][0] + sc[nt][1];
            ls1 += sc[nt][2] + sc[nt][3];
        }
        ls0 += __shfl_xor_sync(0xffffffffu, ls0, 1);
        ls0 += __shfl_xor_sync(0xffffffffu, ls0, 2);
        ls1 += __shfl_xor_sync(0xffffffffu, ls1, 1);
        ls1 += __shfl_xor_sync(0xffffffffu, ls1, 2);
        l0r += ls0; l1r += ls1;

#pragma unroll
        for (int kc = 0; kc < 8; kc++) {
            uint32_t pah[4], pal[4];
#pragma unroll
            for (int half = 0; half < 2; half++) {
                const float* p = sc[2 * kc + half];
#pragma unroll
                for (int rr = 0; rr < 2; rr++) {
                    const float p0 = p[rr * 2 + 0], p1 = p[rr * 2 + 1];
                    const uint32_t hv = pack_bf16x2(p0, p1);
                    const float h0 = __uint_as_float(hv << 16);
                    const float h1 = __uint_as_float(hv & 0xffff0000u);
                    pah[half * 2 + rr] = hv;
                    pal[half * 2 + rr] = pack_bf16x2(p0 - h0, p1 - h1);
                }
            }
#pragma unroll
            for (int dp = 0; dp < 4; dp++) {
                const int vr = kc * 16 + (lane & 15);
                const int vc = 2 * dp + (lane >> 4);
                const uint32_t so = sw2(vr, vc);
                uint32_t vh4[4], vl4[4];
                ldsm4_t(vh4, sVh + so);
                ldsm4_t(vl4, sVl + so);
                mma_bf16(Oa[2 * dp],     pah, &vh4[0]);
                mma_bf16(Oa[2 * dp],     pah, &vl4[0]);
                mma_bf16(Oa[2 * dp],     pal, &vh4[0]);
                mma_bf16(Oa[2 * dp + 1], pah, &vh4[2]);
                mma_bf16(Oa[2 * dp + 1], pah, &vl4[2]);
                mma_bf16(Oa[2 * dp + 1], pal, &vh4[2]);
            }
        }
    }

    const float inv0 = 1.f / l0r, inv1 = 1.f / l1r;
    const size_t row0 = (size_t)(b * S_ + qi0 + wq + r0l) * D_ + h * DK_ + c0l;
    const size_t row1 = row0 + 8 * D_;
#pragma unroll
    for (int dn = 0; dn < 8; dn++) {
        const float o00 = Oa[dn][0] * inv0, o01 = Oa[dn][1] * inv0;
        const float o10 = Oa[dn][2] * inv1, o11 = Oa[dn][3] * inv1;
        const uint32_t hv0 = pack_bf16x2(o00, o01);
        const uint32_t hv1 = pack_bf16x2(o10, o11);
        const float h00 = __uint_as_float(hv0 << 16);
        const float h01 = __uint_as_float(hv0 & 0xffff0000u);
        const float h10 = __uint_as_float(hv1 << 16);
        const float h11 = __uint_as_float(hv1 & 0xffff0000u);
        *reinterpret_cast<uint32_t*>(&g_ah[row0 + dn * 8]) = hv0;
        *reinterpret_cast<uint32_t*>(&g_ah[row1 + dn * 8]) = hv1;
        *reinterpret_cast<uint32_t*>(&g_al[row0 + dn * 8]) =
            pack_bf16x2(o00 - h00, o01 - h01);
        *reinterpret_cast<uint32_t*>(&g_al[row1 + dn * 8]) =
            pack_bf16x2(o10 - h10, o11 - h11);
    }
}

// ---------------------------------------------------------------------------
// Launch
// ---------------------------------------------------------------------------
extern "C" void kernel_launch(void* const* d_in, const int* in_sizes, int n_in,
                              void* d_out, int out_size)
{
    const float* x   = (const float*)d_in[0];
    const float* Wq  = (const float*)d_in[2];
    const float* bq  = (const float*)d_in[3];
    const float* Wk  = (const float*)d_in[4];
    const float* bk  = (const float*)d_in[5];
    const float* Wv  = (const float*)d_in[6];
    const float* bv  = (const float*)d_in[7];
    const float* Wo  = (const float*)d_in[8];
    const float* bo  = (const float*)d_in[9];
    const float* rel = (const float*)d_in[10];
    float* out = (float*)d_out;

    cudaFuncSetAttribute(gemm_qkv_kernel,
                         cudaFuncAttributeMaxDynamicSharedMemorySize,
                         GEMM_SMEM_BYTES);
    cudaFuncSetAttribute(gemm_out_kernel,
                         cudaFuncAttributeMaxDynamicSharedMemorySize,
                         GEMM_SMEM_BYTES);
    cudaFuncSetAttribute(attn_tc_kernel,
                         cudaFuncAttributeMaxDynamicSharedMemorySize,
                         ATTN_SMEM_BYTES);

    split_kernel<<<1024, 256>>>(x);
    dim3 wt(32, 8);
    dim3 wg(32, 32, 4);
    wsplitT_kernel<<<wg, wt>>>(Wq, Wk, Wv, Wo);

    dim3 gq(D_ / 128, MTOT / 128, 3);   // (8, 64, 3)
    gemm_qkv_kernel<<<gq, 256, GEMM_SMEM_BYTES>>>(bq, bk, bv);   // -> q/k/v hi,lo

    dim3 agrid(S_ / 128, H_, B_);       // (4, 16, 16)
    attn_tc_kernel<<<agrid, 256, ATTN_SMEM_BYTES>>>(rel);        // -> ah/al

    dim3 gg(D_ / 128, MTOT / 128);      // (8, 64)
    gemm_out_kernel<<<gg, 256, GEMM_SMEM_BYTES>>>(bo, out);      // -> d_out
}